// round 12
// baseline (speedup 1.0000x reference)
#include <cuda_runtime.h>
#include <math.h>

#define BATCH   256
#define NNODE   128
#define NTOT    32768
#define NTOT2   65536
#define NEDGE   262144
#define NEDGE2  524288
#define FDIM    128
#define HALF    (NTOT*FDIM)
#define LDIMS   61
#define LMAT    16384
#define SK_ITERS 6
#define APAD    132
#define SMEM_G    ((128*128 + 128*64)*4)                    // 96KB: As + Bs(half-N)
#define SMEM_AGG  (128*128*4)                               // 64KB H tile
#define SMEM_FUSE ((128*128 + 128*128 + 128*APAD)*4)

typedef unsigned long long u64;

struct Scratch {
    float feat[NTOT2*FDIM];
    float fa[NTOT2*FDIM];
    float fb[NTOT2*FDIM];
    float fc[NTOT2*FDIM];
    float htmp[NTOT2*FDIM];
    float cw[NEDGE2];
    float dinv[NTOT2];
    float scores[BATCH*1024];
    int csrc[NEDGE2];
    int deg[NTOT2];
    int fill[NTOT2];
    int rp[NTOT2+1];
    int bsum[64];
};
__device__ Scratch g_scratch;

// ---------------- f32x2 packed FMA helpers ----------------
__device__ __forceinline__ u64 pack2(float v) {
    u64 r; asm("mov.b64 %0, {%1, %1};" : "=l"(r) : "f"(v)); return r;
}
__device__ __forceinline__ void ffma2(u64& d, u64 a, u64 b) {
    asm("fma.rn.f32x2 %0, %1, %2, %3;" : "=l"(d) : "l"(a), "l"(b), "l"(d));
}
__device__ __forceinline__ float2 unpack2(u64 v) {
    float2 f; asm("mov.b64 {%0, %1}, %2;" : "=f"(f.x), "=f"(f.y) : "l"(v)); return f;
}
__device__ __forceinline__ float fcomp(float4 v, int kk) {
    return (kk==0) ? v.x : (kk==1) ? v.y : (kk==2) ? v.z : v.w;
}

// FMA-pipe sigmoid (no MUFU)
__device__ __forceinline__ float fast_sigmoid(float z) {
    float az = fminf(fabsf(z), 80.0f);
    float t = az * 1.4426950408889634f;
    float n = rintf(t);
    float w = -(t - n) * 0.6931471805599453f;
    float p = fmaf(w, 0.00833333377f, 0.0416666679f);
    p = fmaf(w, p, 0.16666667f);
    p = fmaf(w, p, 0.5f);
    p = fmaf(w, p, 1.0f);
    p = fmaf(w, p, 1.0f);
    float e = p * __int_as_float((127 - (int)n) << 23);
    float d = 1.0f + e;
    float y = fmaf(-0.5f, d, 1.45711f);
    y = y * fmaf(-d, y, 2.0f);
    y = y * fmaf(-d, y, 2.0f);
    y = y * fmaf(-d, y, 2.0f);
    return (z >= 0.0f) ? y : e * y;
}

// ---------------- CSR build ----------------
__global__ void zero_kernel(int* __restrict__ deg, int* __restrict__ fill) {
    int i = blockIdx.x*blockDim.x + threadIdx.x;
    int4 z = {0,0,0,0};
    ((int4*)deg)[i] = z;
    ((int4*)fill)[i] = z;
}
__global__ void count_kernel(const int* __restrict__ dst1, const int* __restrict__ dst2,
                             int* __restrict__ deg) {
    int e = blockIdx.x*blockDim.x + threadIdx.x;
    if (e < NEDGE) atomicAdd(&deg[dst1[e]], 1);
    else if (e < NEDGE2) atomicAdd(&deg[dst2[e - NEDGE] + NTOT], 1);
}
__global__ void scan_block_kernel(const int* __restrict__ deg, int* __restrict__ rp,
                                  float* __restrict__ dinv, int* __restrict__ bsum) {
    __shared__ int ws[32];
    int tid = threadIdx.x, lane = tid & 31, wid = tid >> 5;
    int gi = blockIdx.x*1024 + tid;
    int v = deg[gi];
    dinv[gi] = rsqrtf((float)(v + 1));
    int x = v;
    #pragma unroll
    for (int off = 1; off < 32; off <<= 1) {
        int t = __shfl_up_sync(0xffffffffu, x, off);
        if (lane >= off) x += t;
    }
    if (lane == 31) ws[wid] = x;
    __syncthreads();
    if (wid == 0) {
        int y = ws[lane];
        #pragma unroll
        for (int off = 1; off < 32; off <<= 1) {
            int t = __shfl_up_sync(0xffffffffu, y, off);
            if (lane >= off) y += t;
        }
        ws[lane] = y;
    }
    __syncthreads();
    int woff = (wid > 0) ? ws[wid-1] : 0;
    rp[gi] = woff + x - v;
    if (tid == 1023) bsum[blockIdx.x] = woff + x;
}
__global__ void scan_add_kernel(int* __restrict__ rp, const int* __restrict__ bsum) {
    __shared__ int off_s;
    if (threadIdx.x == 0) {
        int acc = 0;
        for (int i = 0; i < blockIdx.x; ++i) acc += bsum[i];
        off_s = acc;
    }
    __syncthreads();
    int gi = blockIdx.x*1024 + threadIdx.x;
    rp[gi] += off_s;
    if (gi == 0) rp[NTOT2] = NEDGE2;
}
__global__ void scatter_kernel(const int* __restrict__ src1, const int* __restrict__ dst1,
                               const int* __restrict__ src2, const int* __restrict__ dst2,
                               const int* __restrict__ rp, int* __restrict__ fill,
                               const float* __restrict__ dinv,
                               int* __restrict__ csrc, float* __restrict__ cw) {
    int e = blockIdx.x*blockDim.x + threadIdx.x;
    if (e >= NEDGE2) return;
    int s, d;
    if (e < NEDGE) { s = src1[e]; d = dst1[e]; }
    else { s = src2[e - NEDGE] + NTOT; d = dst2[e - NEDGE] + NTOT; }
    int pos = rp[d] + atomicAdd(&fill[d], 1);
    csrc[pos] = s;
    cw[pos] = dinv[s] * dinv[d];
}

// ---------------- initial features ----------------
__global__ void init_feat_kernel(const float* __restrict__ x1, const int* __restrict__ c1,
                                 const float* __restrict__ rw1,
                                 const float* __restrict__ x2, const int* __restrict__ c2,
                                 const float* __restrict__ rw2,
                                 const float* __restrict__ emb,
                                 const float* __restrict__ W, const float* __restrict__ bias,
                                 float* __restrict__ out) {
    int which = blockIdx.x >> 14;
    int bi = blockIdx.x & 16383;
    const float* x  = which ? x2 : x1;
    const int*   ce = which ? c2 : c1;
    const float* rw = which ? rw2 : rw1;
    int half = threadIdx.x >> 7;
    int f = threadIdx.x & 127;
    int node = bi*2 + half;
    __shared__ float a[2][LDIMS];
    if (f < 29)      a[half][f] = x[node*29 + f];
    else if (f < 45) a[half][f] = emb[ce[node]*16 + (f-29)];
    else if (f < 61) a[half][f] = rw[node*16 + (f-45)];
    __syncthreads();
    float acc = bias[f];
    #pragma unroll
    for (int c = 0; c < LDIMS; ++c)
        acc = fmaf(a[half][c], W[c*FDIM + f], acc);
    out[((size_t)(which*NTOT + node) << 7) + f] = fmaxf(acc, 0.0f);
}

// ---------------- GEMM: M=128 tile, N=64 half, 256 thr, 8x4 microtile ----------------
// grid = (NTOT2/128)*2; bid>>1 = m-tile, bid&1 = n-half. 96KB smem, 2 CTAs/SM (16 warps).
__global__ void __launch_bounds__(256, 2)
gemm_aw_kernel(const float* __restrict__ A, const float* __restrict__ W,
               float* __restrict__ C, int relu_a) {
    extern __shared__ float sm[];
    float* As = sm;               // [128][128] row-major
    float* Bs = sm + 128*128;     // [128][64]
    int tid = threadIdx.x;
    size_t m0 = (size_t)(blockIdx.x >> 1) << 7;
    int nh = (blockIdx.x & 1) << 6;

    {
        int r = tid >> 5, c4 = (tid & 31) << 2;
        #pragma unroll
        for (int it = 0; it < 16; ++it) {
            int m = (it << 3) + r;
            float4 v = *(const float4*)(A + (m0 + m)*FDIM + c4);
            if (relu_a) { v.x=fmaxf(v.x,0.f); v.y=fmaxf(v.y,0.f); v.z=fmaxf(v.z,0.f); v.w=fmaxf(v.w,0.f); }
            *(float4*)(As + (m << 7) + c4) = v;
        }
        int kb = tid >> 4, c4b = (tid & 15) << 2;
        #pragma unroll
        for (int it = 0; it < 8; ++it) {
            int k = (it << 4) + kb;
            *(float4*)(Bs + (k << 6) + c4b) = *(const float4*)(W + k*FDIM + nh + c4b);
        }
    }
    __syncthreads();

    int tx = tid & 15, ty = tid >> 4;      // ty 0..15 -> rows ty*8..+7
    u64 acc[8][2] = {};
    #pragma unroll 2
    for (int k0 = 0; k0 < 128; k0 += 4) {
        float4 a4[8];
        #pragma unroll
        for (int i = 0; i < 8; ++i)
            a4[i] = *(float4*)(As + ((ty<<3) + i)*128 + k0);   // broadcast
        #pragma unroll
        for (int kk = 0; kk < 4; ++kk) {
            ulonglong2 q = *(ulonglong2*)(Bs + ((k0+kk) << 6) + (tx<<2));
            u64 b0 = q.x, b1 = q.y;
            #pragma unroll
            for (int i = 0; i < 8; ++i) {
                u64 au = pack2(fcomp(a4[i], kk));
                ffma2(acc[i][0], au, b0);
                ffma2(acc[i][1], au, b1);
            }
        }
    }
    #pragma unroll
    for (int i = 0; i < 8; ++i) {
        int row = (ty<<3) + i;
        float2 p0 = unpack2(acc[i][0]), p1 = unpack2(acc[i][1]);
        float4 o = {p0.x, p0.y, p1.x, p1.y};
        *(float4*)(C + (m0 + row)*FDIM + nh + (tx<<2)) = o;
    }
}

// ---------------- GCN aggregation: per-graph smem-staged gather ----------------
// CTA g stages H[g] (64KB) in smem; warp w handles nodes w*16..+15.
__global__ void __launch_bounds__(256, 3)
agg_kernel(const float* __restrict__ h, const float* __restrict__ bias,
           const int* __restrict__ rp, const int* __restrict__ csrc,
           const float* __restrict__ cw, const float* __restrict__ dinv,
           float* __restrict__ out) {
    extern __shared__ float Hs[];
    float4* H4 = (float4*)Hs;
    int tid = threadIdx.x;
    int g = blockIdx.x;
    int base = g << 7;
    const float4* hsrc = (const float4*)(h + ((size_t)base << 7));
    #pragma unroll
    for (int i = 0; i < 16; ++i)
        H4[(i << 8) + tid] = hsrc[(i << 8) + tid];
    __syncthreads();

    int w = tid >> 5, lane = tid & 31;
    float4 bv = ((const float4*)bias)[lane];
    for (int p = 0; p < 16; ++p) {
        int m = (w << 4) + p;
        float di = dinv[base + m];
        float w2 = di * di;
        float4 hm = H4[(m << 5) + lane];
        float4 acc;
        acc.x = fmaf(hm.x, w2, bv.x); acc.y = fmaf(hm.y, w2, bv.y);
        acc.z = fmaf(hm.z, w2, bv.z); acc.w = fmaf(hm.w, w2, bv.w);
        int e = rp[base + m], e1 = rp[base + m + 1];
        for (; e + 4 <= e1; e += 4) {
            int s0 = csrc[e] - base, s1 = csrc[e+1] - base;
            int s2 = csrc[e+2] - base, s3 = csrc[e+3] - base;
            float w0 = cw[e], w1 = cw[e+1], wv2 = cw[e+2], w3 = cw[e+3];
            float4 v0 = H4[(s0 << 5) + lane];
            float4 v1 = H4[(s1 << 5) + lane];
            float4 v2 = H4[(s2 << 5) + lane];
            float4 v3 = H4[(s3 << 5) + lane];
            acc.x = fmaf(v0.x, w0, acc.x); acc.y = fmaf(v0.y, w0, acc.y);
            acc.z = fmaf(v0.z, w0, acc.z); acc.w = fmaf(v0.w, w0, acc.w);
            acc.x = fmaf(v1.x, w1, acc.x); acc.y = fmaf(v1.y, w1, acc.y);
            acc.z = fmaf(v1.z, w1, acc.z); acc.w = fmaf(v1.w, w1, acc.w);
            acc.x = fmaf(v2.x, wv2, acc.x); acc.y = fmaf(v2.y, wv2, acc.y);
            acc.z = fmaf(v2.z, wv2, acc.z); acc.w = fmaf(v2.w, wv2, acc.w);
            acc.x = fmaf(v3.x, w3, acc.x); acc.y = fmaf(v3.y, w3, acc.y);
            acc.z = fmaf(v3.z, w3, acc.z); acc.w = fmaf(v3.w, w3, acc.w);
        }
        for (; e < e1; ++e) {
            int s = csrc[e] - base;
            float we = cw[e];
            float4 v = H4[(s << 5) + lane];
            acc.x = fmaf(v.x, we, acc.x); acc.y = fmaf(v.y, we, acc.y);
            acc.z = fmaf(v.z, we, acc.z); acc.w = fmaf(v.w, we, acc.w);
        }
        ((float4*)out)[((size_t)(base + m) << 5) + lane] = acc;
    }
}

// ---------------- fused affinity + 2-anchor Sinkhorn ----------------
__global__ void __launch_bounds__(256, 1)
aff_sink_kernel(const float* __restrict__ feat, const float* __restrict__ fc,
                const float* __restrict__ Aaff, const int* __restrict__ topk,
                float* __restrict__ sim1, float* __restrict__ sim2) {
    extern __shared__ float smf[];
    float* As = smf;                    // [128][128]
    float* Ws = smf + 128*128;          // [128][128]
    float* Bs = Ws + 128*128;           // [128][APAD]
    __shared__ float rmn[8], rmx[8], rbuf[8], bc[2];

    int tid = threadIdx.x;
    int lane = tid & 31, wid = tid >> 5;
    int which = blockIdx.x >> 8;
    int b = blockIdx.x & 255;
    const float* base = which ? fc : feat;
    const float* Xa = base + (size_t)b * LMAT;
    const float* Xb = base + HALF + (size_t)b * LMAT;
    float* P = (which ? sim2 : sim1) + (size_t)b * LMAT;

    int lr = tid >> 5, lc = (tid & 31) << 2;
    #pragma unroll
    for (int it = 0; it < 16; ++it) {
        int m = (it << 3) + lr;
        *(float4*)(As + (m << 7) + lc) = *(const float4*)(Xa + (m << 7) + lc);
        *(float4*)(Ws + (m << 7) + lc) = *(const float4*)(Aaff + (m << 7) + lc);
        float4 vb = *(const float4*)(Xb + (m << 7) + lc);
        Bs[(lc+0)*APAD + m] = vb.x; Bs[(lc+1)*APAD + m] = vb.y;
        Bs[(lc+2)*APAD + m] = vb.z; Bs[(lc+3)*APAD + m] = vb.w;
    }
    __syncthreads();
    int tx = tid & 15, ty = tid >> 4;

    // loop1: T = Xa @ Aaff
    u64 acc[8][4] = {};
    #pragma unroll 2
    for (int k0 = 0; k0 < 128; k0 += 4) {
        float4 a4[8];
        #pragma unroll
        for (int i = 0; i < 8; ++i)
            a4[i] = *(float4*)(As + ((ty<<3) + i)*128 + k0);
        #pragma unroll
        for (int kk = 0; kk < 4; ++kk) {
            ulonglong2 q0 = *(ulonglong2*)(Ws + ((k0+kk) << 7) + (tx<<2));
            ulonglong2 q1 = *(ulonglong2*)(Ws + ((k0+kk) << 7) + 64 + (tx<<2));
            u64 bu[4] = {q0.x, q0.y, q1.x, q1.y};
            #pragma unroll
            for (int i = 0; i < 8; ++i) {
                u64 au = pack2(fcomp(a4[i], kk));
                #pragma unroll
                for (int j = 0; j < 4; ++j) ffma2(acc[i][j], au, bu[j]);
            }
        }
    }
    __syncthreads();
    #pragma unroll
    for (int i = 0; i < 8; ++i) {
        int row = (ty<<3) + i;
        float2 p0 = unpack2(acc[i][0]), p1 = unpack2(acc[i][1]);
        float2 p2 = unpack2(acc[i][2]), p3 = unpack2(acc[i][3]);
        float4 o0 = {p0.x,p0.y,p1.x,p1.y};
        float4 o1 = {p2.x,p2.y,p3.x,p3.y};
        *(float4*)(As + (row << 7) + (tx<<2)) = o0;
        *(float4*)(As + (row << 7) + 64 + (tx<<2)) = o1;
    }
    __syncthreads();

    // loop2: C = T @ Xb^T
    #pragma unroll
    for (int i = 0; i < 8; ++i)
        #pragma unroll
        for (int j = 0; j < 4; ++j) acc[i][j] = 0ull;
    #pragma unroll 2
    for (int k0 = 0; k0 < 128; k0 += 4) {
        float4 a4[8];
        #pragma unroll
        for (int i = 0; i < 8; ++i)
            a4[i] = *(float4*)(As + ((ty<<3) + i)*128 + k0);
        #pragma unroll
        for (int kk = 0; kk < 4; ++kk) {
            ulonglong2 q0 = *(ulonglong2*)(Bs + (k0+kk)*APAD + (tx<<2));
            ulonglong2 q1 = *(ulonglong2*)(Bs + (k0+kk)*APAD + 64 + (tx<<2));
            u64 bu[4] = {q0.x, q0.y, q1.x, q1.y};
            #pragma unroll
            for (int i = 0; i < 8; ++i) {
                u64 au = pack2(fcomp(a4[i], kk));
                #pragma unroll
                for (int j = 0; j < 4; ++j) ffma2(acc[i][j], au, bu[j]);
            }
        }
    }

    float za[64];
    float mn = 3.4e38f, mx = -3.4e38f;
    #pragma unroll
    for (int i = 0; i < 8; ++i)
        #pragma unroll
        for (int jj = 0; jj < 4; ++jj) {
            float2 p = unpack2(acc[i][jj]);
            za[i*8 + jj*2 + 0] = p.x;
            za[i*8 + jj*2 + 1] = p.y;
            mn = fminf(mn, fminf(p.x, p.y));
            mx = fmaxf(mx, fmaxf(p.x, p.y));
        }
    #pragma unroll
    for (int off = 16; off; off >>= 1) {
        mn = fminf(mn, __shfl_xor_sync(0xffffffffu, mn, off));
        mx = fmaxf(mx, __shfl_xor_sync(0xffffffffu, mx, off));
    }
    if (lane == 0) { rmn[wid] = mn; rmx[wid] = mx; }
    __syncthreads();
    if (tid == 0) {
        float m1 = rmn[0], m2 = rmx[0];
        for (int q = 1; q < 8; ++q) { m1 = fminf(m1, rmn[q]); m2 = fmaxf(m2, rmx[q]); }
        bc[0] = m1 + m2;
    }
    __syncthreads();
    float Cc = bc[0];
    #pragma unroll
    for (int l = 0; l < 64; ++l) za[l] = fmaf(2.0f, za[l], -Cc);

    float kf = 0.5f * (float)(*topk);
    const float Lf = (float)LMAT;
    float lk = logf(kf / (Lf - kf));
    float delta = 0.0f, scale = 0.0f;
    for (int it = 0; it < SK_ITERS; ++it) {
        float T = 0.0f;
        if (it < SK_ITERS - 1) {
            #pragma unroll
            for (int l = 0; l < 64; ++l) T += fast_sigmoid(za[l] + delta);
        } else {
            #pragma unroll
            for (int l = 0; l < 64; ++l) { za[l] = fast_sigmoid(za[l] + delta); T += za[l]; }
        }
        #pragma unroll
        for (int off = 16; off; off >>= 1)
            T += __shfl_xor_sync(0xffffffffu, T, off);
        if (lane == 0) rbuf[wid] = T;
        __syncthreads();
        if (tid == 0) {
            float s = 0.0f;
            for (int q = 0; q < 8; ++q) s += rbuf[q];
            bc[1] = s;
        }
        __syncthreads();
        float Tall = bc[1];
        if (it < SK_ITERS - 1) delta += lk + logf((Lf - Tall) / Tall);
        else scale = kf / Tall;
        __syncthreads();
    }

    #pragma unroll
    for (int i = 0; i < 8; ++i) {
        int row = (ty<<3) + i;
        #pragma unroll
        for (int jj = 0; jj < 4; ++jj) {
            int c0 = ((jj < 2) ? 0 : 64) + (tx<<2) + 2*(jj & 1);
            float2 o;
            o.x = scale * za[i*8 + jj*2 + 0];
            o.y = scale * za[i*8 + jj*2 + 1];
            *(float2*)(P + (row << 7) + c0) = o;
        }
    }
}

// ---------------- graph features + scorer ----------------
__global__ void gf_kernel(const float* __restrict__ feat, const float* __restrict__ fa,
                          const float* __restrict__ fb, const float* __restrict__ fcv,
                          float* __restrict__ scores) {
    int b = blockIdx.x;
    int tid = threadIdx.x;
    int job = tid >> 5, lane = tid & 31;
    int buf = job & 3;
    const float* p = (buf==0?feat:buf==1?fa:buf==2?fb:fcv);
    if (job < 4) {
        const float4* p4 = (const float4*)(p + (((size_t)b*NNODE) << 7)) + lane;
        float4 s = {0,0,0,0};
        #pragma unroll 4
        for (int n = 0; n < NNODE; ++n) {
            float4 v = p4[n << 5];
            s.x += v.x; s.y += v.y; s.z += v.z; s.w += v.w;
        }
        ((float4*)(scores + b*1024 + buf*128))[lane] = s;
    } else {
        const float4* p4 = (const float4*)(p + HALF + (((size_t)b*NNODE) << 7)) + lane;
        float4 m = {-3.4e38f,-3.4e38f,-3.4e38f,-3.4e38f};
        #pragma unroll 4
        for (int n = 0; n < NNODE; ++n) {
            float4 v = p4[n << 5];
            m.x = fmaxf(m.x, v.x); m.y = fmaxf(m.y, v.y);
            m.z = fmaxf(m.z, v.z); m.w = fmaxf(m.w, v.w);
        }
        ((float4*)(scores + b*1024 + 512 + buf*128))[lane] = m;
    }
}

__global__ void score_kernel(const float* __restrict__ scores,
                             const float* __restrict__ W1, const float* __restrict__ b1,
                             const float* __restrict__ W2, const float* __restrict__ b2,
                             float* __restrict__ ged) {
    int b = blockIdx.x;
    int j = threadIdx.x;
    __shared__ float sv[1024];
    __shared__ float rr[2];
    for (int i = j; i < 1024; i += 64) sv[i] = scores[b*1024 + i];
    __syncthreads();
    float acc = b1[j];
    #pragma unroll 8
    for (int i = 0; i < 1024; ++i)
        acc = fmaf(sv[i], W1[i*64 + j], acc);
    float pv = fmaxf(acc, 0.0f) * W2[j];
    #pragma unroll
    for (int off = 16; off; off >>= 1)
        pv += __shfl_xor_sync(0xffffffffu, pv, off);
    if ((j & 31) == 0) rr[j >> 5] = pv;
    __syncthreads();
    if (j == 0) {
        float v = rr[0] + rr[1] + b2[0];
        ged[b] = 1.0f / (1.0f + expf(-v));
    }
}

// ---------------- streams/events (created once, on the uncaptured first call) ----------------
static cudaStream_t g_s1 = nullptr;
static cudaEvent_t g_evFork = nullptr, g_evCsr = nullptr, g_evFc = nullptr, g_evTail = nullptr;

extern "C" void kernel_launch(void* const* d_in, const int* in_sizes, int n_in,
                              void* d_out, int out_size) {
    const float* x1    = (const float*)d_in[0];
    const int*   cent1 = (const int*)d_in[1];
    const float* rw1   = (const float*)d_in[2];
    const int*   src1  = (const int*)d_in[3];
    const int*   dst1  = (const int*)d_in[4];
    const float* x2    = (const float*)d_in[5];
    const int*   cent2 = (const int*)d_in[6];
    const float* rw2   = (const float*)d_in[7];
    const int*   src2  = (const int*)d_in[8];
    const int*   dst2  = (const int*)d_in[9];
    const float* emb   = (const float*)d_in[10];
    const float* initW = (const float*)d_in[11];
    const float* initb = (const float*)d_in[12];
    const float* W1    = (const float*)d_in[13];
    const float* b1    = (const float*)d_in[14];
    const float* W2    = (const float*)d_in[15];
    const float* b2    = (const float*)d_in[16];
    const float* W3    = (const float*)d_in[17];
    const float* b3    = (const float*)d_in[18];
    const float* Aaff  = (const float*)d_in[19];
    const float* scW1  = (const float*)d_in[20];
    const float* scb1  = (const float*)d_in[21];
    const float* scW2  = (const float*)d_in[22];
    const float* scb2  = (const float*)d_in[23];
    const int*   topk  = (const int*)d_in[24];

    Scratch* S = nullptr;
    cudaGetSymbolAddress((void**)&S, g_scratch);

    float* out  = (float*)d_out;
    float* ged  = out;
    float* sim1 = out + BATCH;
    float* sim2 = out + BATCH + (size_t)BATCH * LMAT;

    if (g_s1 == nullptr) {
        cudaStreamCreateWithFlags(&g_s1, cudaStreamNonBlocking);
        cudaEventCreateWithFlags(&g_evFork, cudaEventDisableTiming);
        cudaEventCreateWithFlags(&g_evCsr,  cudaEventDisableTiming);
        cudaEventCreateWithFlags(&g_evFc,   cudaEventDisableTiming);
        cudaEventCreateWithFlags(&g_evTail, cudaEventDisableTiming);
    }
    cudaStream_t s0 = 0, s1 = g_s1;

    cudaFuncSetAttribute(gemm_aw_kernel,  cudaFuncAttributeMaxDynamicSharedMemorySize, SMEM_G);
    cudaFuncSetAttribute(agg_kernel,      cudaFuncAttributeMaxDynamicSharedMemorySize, SMEM_AGG);
    cudaFuncSetAttribute(aff_sink_kernel, cudaFuncAttributeMaxDynamicSharedMemorySize, SMEM_FUSE);

    // fork: s1 builds CSR while s0 does init features + GEMM #1
    cudaEventRecord(g_evFork, s0);
    cudaStreamWaitEvent(s1, g_evFork, 0);

    init_feat_kernel<<<NTOT, 256, 0, s0>>>(x1, cent1, rw1, x2, cent2, rw2,
                                           emb, initW, initb, S->feat);            // 1 (s0)
    zero_kernel<<<64, 256, 0, s1>>>(S->deg, S->fill);                              // 2 (s1)
    count_kernel<<<NEDGE2/256, 256, 0, s1>>>(dst1, dst2, S->deg);                  // 3 (s1)
    gemm_aw_kernel<<<NTOT2/64, 256, SMEM_G, s0>>>(S->feat, W1, S->htmp, 0);        // 4 (s0) <- profiled
    scan_block_kernel<<<64, 1024, 0, s1>>>(S->deg, S->rp, S->dinv, S->bsum);       // 5 (s1)
    scan_add_kernel<<<64, 1024, 0, s1>>>(S->rp, S->bsum);                          // 6 (s1)
    scatter_kernel<<<NEDGE2/256, 256, 0, s1>>>(src1, dst1, src2, dst2, S->rp,
                                               S->fill, S->dinv, S->csrc, S->cw);  // 7 (s1)
    cudaEventRecord(g_evCsr, s1);
    cudaStreamWaitEvent(s0, g_evCsr, 0);   // join: aggregation needs CSR

    agg_kernel<<<512, 256, SMEM_AGG, s0>>>(S->htmp, b1, S->rp, S->csrc, S->cw, S->dinv, S->fa);
    gemm_aw_kernel<<<NTOT2/64, 256, SMEM_G, s0>>>(S->fa, W2, S->htmp, 1);
    agg_kernel<<<512, 256, SMEM_AGG, s0>>>(S->htmp, b2, S->rp, S->csrc, S->cw, S->dinv, S->fb);
    gemm_aw_kernel<<<NTOT2/64, 256, SMEM_G, s0>>>(S->fb, W3, S->htmp, 1);
    agg_kernel<<<512, 256, SMEM_AGG, s0>>>(S->htmp, b3, S->rp, S->csrc, S->cw, S->dinv, S->fc);

    // fork: gf + scorer on s1 concurrent with aff_sink on s0
    cudaEventRecord(g_evFc, s0);
    cudaStreamWaitEvent(s1, g_evFc, 0);
    aff_sink_kernel<<<2*BATCH, 256, SMEM_FUSE, s0>>>(S->feat, S->fc, Aaff, topk, sim1, sim2);
    gf_kernel<<<BATCH, 256, 0, s1>>>(S->feat, S->fa, S->fb, S->fc, S->scores);
    score_kernel<<<BATCH, 64, 0, s1>>>(S->scores, scW1, scb1, scW2, scb2, ged);
    cudaEventRecord(g_evTail, s1);
    cudaStreamWaitEvent(s0, g_evTail, 0);  // join so the graph's leaf is on s0
}

// round 13
// speedup vs baseline: 1.0279x; 1.0279x over previous
#include <cuda_runtime.h>
#include <math.h>

#define BATCH   256
#define NNODE   128
#define NTOT    32768
#define NTOT2   65536
#define NEDGE   262144
#define NEDGE2  524288
#define FDIM    128
#define HALF    (NTOT*FDIM)
#define LDIMS   61
#define LMAT    16384
#define SK_ITERS 6
#define APAD    132
#define SMEM_G    ((64*128 + 128*128)*4)                    // 96KB (R11 proven)
#define SMEM_AGG  (128*128*4)                               // 64KB H tile
#define SMEM_FUSE ((128*128 + 128*128 + 128*APAD)*4)

typedef unsigned long long u64;

struct Scratch {
    float feat[NTOT2*FDIM];
    float fa[NTOT2*FDIM];
    float fb[NTOT2*FDIM];
    float fc[NTOT2*FDIM];
    float htmp[NTOT2*FDIM];
    float cw[NEDGE2];
    float dinv[NTOT2];
    float scores[BATCH*1024];
    int csrc[NEDGE2];
    int deg[NTOT2];
    int fill[NTOT2];
    int rp[NTOT2+1];
    int bsum[64];
};
__device__ Scratch g_scratch;

// ---------------- f32x2 packed FMA helpers ----------------
__device__ __forceinline__ u64 pack2(float v) {
    u64 r; asm("mov.b64 %0, {%1, %1};" : "=l"(r) : "f"(v)); return r;
}
__device__ __forceinline__ void ffma2(u64& d, u64 a, u64 b) {
    asm("fma.rn.f32x2 %0, %1, %2, %3;" : "=l"(d) : "l"(a), "l"(b), "l"(d));
}
__device__ __forceinline__ float2 unpack2(u64 v) {
    float2 f; asm("mov.b64 {%0, %1}, %2;" : "=f"(f.x), "=f"(f.y) : "l"(v)); return f;
}
__device__ __forceinline__ float fcomp(float4 v, int kk) {
    return (kk==0) ? v.x : (kk==1) ? v.y : (kk==2) ? v.z : v.w;
}

// FMA-pipe sigmoid (no MUFU)
__device__ __forceinline__ float fast_sigmoid(float z) {
    float az = fminf(fabsf(z), 80.0f);
    float t = az * 1.4426950408889634f;
    float n = rintf(t);
    float w = -(t - n) * 0.6931471805599453f;
    float p = fmaf(w, 0.00833333377f, 0.0416666679f);
    p = fmaf(w, p, 0.16666667f);
    p = fmaf(w, p, 0.5f);
    p = fmaf(w, p, 1.0f);
    p = fmaf(w, p, 1.0f);
    float e = p * __int_as_float((127 - (int)n) << 23);
    float d = 1.0f + e;
    float y = fmaf(-0.5f, d, 1.45711f);
    y = y * fmaf(-d, y, 2.0f);
    y = y * fmaf(-d, y, 2.0f);
    y = y * fmaf(-d, y, 2.0f);
    return (z >= 0.0f) ? y : e * y;
}

// ---------------- CSR build ----------------
__global__ void zero_kernel(int* __restrict__ deg, int* __restrict__ fill) {
    int i = blockIdx.x*blockDim.x + threadIdx.x;
    int4 z = {0,0,0,0};
    ((int4*)deg)[i] = z;
    ((int4*)fill)[i] = z;
}
__global__ void count_kernel(const int* __restrict__ dst1, const int* __restrict__ dst2,
                             int* __restrict__ deg) {
    int e = blockIdx.x*blockDim.x + threadIdx.x;
    if (e < NEDGE) atomicAdd(&deg[dst1[e]], 1);
    else if (e < NEDGE2) atomicAdd(&deg[dst2[e - NEDGE] + NTOT], 1);
}
__global__ void scan_block_kernel(const int* __restrict__ deg, int* __restrict__ rp,
                                  float* __restrict__ dinv, int* __restrict__ bsum) {
    __shared__ int ws[32];
    int tid = threadIdx.x, lane = tid & 31, wid = tid >> 5;
    int gi = blockIdx.x*1024 + tid;
    int v = deg[gi];
    dinv[gi] = rsqrtf((float)(v + 1));
    int x = v;
    #pragma unroll
    for (int off = 1; off < 32; off <<= 1) {
        int t = __shfl_up_sync(0xffffffffu, x, off);
        if (lane >= off) x += t;
    }
    if (lane == 31) ws[wid] = x;
    __syncthreads();
    if (wid == 0) {
        int y = ws[lane];
        #pragma unroll
        for (int off = 1; off < 32; off <<= 1) {
            int t = __shfl_up_sync(0xffffffffu, y, off);
            if (lane >= off) y += t;
        }
        ws[lane] = y;
    }
    __syncthreads();
    int woff = (wid > 0) ? ws[wid-1] : 0;
    rp[gi] = woff + x - v;
    if (tid == 1023) bsum[blockIdx.x] = woff + x;
}
__global__ void scan_add_kernel(int* __restrict__ rp, const int* __restrict__ bsum) {
    __shared__ int off_s;
    if (threadIdx.x == 0) {
        int acc = 0;
        for (int i = 0; i < blockIdx.x; ++i) acc += bsum[i];
        off_s = acc;
    }
    __syncthreads();
    int gi = blockIdx.x*1024 + threadIdx.x;
    rp[gi] += off_s;
    if (gi == 0) rp[NTOT2] = NEDGE2;
}
__global__ void scatter_kernel(const int* __restrict__ src1, const int* __restrict__ dst1,
                               const int* __restrict__ src2, const int* __restrict__ dst2,
                               const int* __restrict__ rp, int* __restrict__ fill,
                               const float* __restrict__ dinv,
                               int* __restrict__ csrc, float* __restrict__ cw) {
    int e = blockIdx.x*blockDim.x + threadIdx.x;
    if (e >= NEDGE2) return;
    int s, d;
    if (e < NEDGE) { s = src1[e]; d = dst1[e]; }
    else { s = src2[e - NEDGE] + NTOT; d = dst2[e - NEDGE] + NTOT; }
    int pos = rp[d] + atomicAdd(&fill[d], 1);
    csrc[pos] = s;
    cw[pos] = dinv[s] * dinv[d];
}

// ---------------- initial features ----------------
__global__ void init_feat_kernel(const float* __restrict__ x1, const int* __restrict__ c1,
                                 const float* __restrict__ rw1,
                                 const float* __restrict__ x2, const int* __restrict__ c2,
                                 const float* __restrict__ rw2,
                                 const float* __restrict__ emb,
                                 const float* __restrict__ W, const float* __restrict__ bias,
                                 float* __restrict__ out) {
    int which = blockIdx.x >> 14;
    int bi = blockIdx.x & 16383;
    const float* x  = which ? x2 : x1;
    const int*   ce = which ? c2 : c1;
    const float* rw = which ? rw2 : rw1;
    int half = threadIdx.x >> 7;
    int f = threadIdx.x & 127;
    int node = bi*2 + half;
    __shared__ float a[2][LDIMS];
    if (f < 29)      a[half][f] = x[node*29 + f];
    else if (f < 45) a[half][f] = emb[ce[node]*16 + (f-29)];
    else if (f < 61) a[half][f] = rw[node*16 + (f-45)];
    __syncthreads();
    float acc = bias[f];
    #pragma unroll
    for (int c = 0; c < LDIMS; ++c)
        acc = fmaf(a[half][c], W[c*FDIM + f], acc);
    out[((size_t)(which*NTOT + node) << 7) + f] = fmaxf(acc, 0.0f);
}

// ---------------- GEMM C[64-tile,128] = op(A) @ W, 128 thr, 8x8 microtile (R11) ----------------
__global__ void __launch_bounds__(128, 2)
gemm_aw_kernel(const float* __restrict__ A, const float* __restrict__ W,
               float* __restrict__ C, int relu_a) {
    extern __shared__ float sm[];
    float* As = sm;               // [64][128] row-major
    float* Bs = sm + 64*128;      // [128][128]
    int tid = threadIdx.x;
    size_t m0 = (size_t)blockIdx.x * 64;

    {
        int r = tid >> 5, c4 = (tid & 31) << 2;
        #pragma unroll
        for (int it = 0; it < 16; ++it) {
            int m = (it << 2) + r;
            float4 v = *(const float4*)(A + (m0 + m)*FDIM + c4);
            if (relu_a) { v.x=fmaxf(v.x,0.f); v.y=fmaxf(v.y,0.f); v.z=fmaxf(v.z,0.f); v.w=fmaxf(v.w,0.f); }
            *(float4*)(As + (m << 7) + c4) = v;
        }
        #pragma unroll
        for (int it = 0; it < 32; ++it) {
            int m = (it << 2) + r;
            *(float4*)(Bs + (m << 7) + c4) = *(const float4*)(W + m*FDIM + c4);
        }
    }
    __syncthreads();

    int tx = tid & 15, ty = tid >> 4;      // ty 0..7 -> rows ty*8..+7
    u64 acc[8][4] = {};
    #pragma unroll 2
    for (int k0 = 0; k0 < 128; k0 += 4) {
        float4 a4[8];
        #pragma unroll
        for (int i = 0; i < 8; ++i)
            a4[i] = *(float4*)(As + ((ty<<3) + i)*128 + k0);   // broadcast
        #pragma unroll
        for (int kk = 0; kk < 4; ++kk) {
            ulonglong2 q0 = *(ulonglong2*)(Bs + ((k0+kk) << 7) + (tx<<2));
            ulonglong2 q1 = *(ulonglong2*)(Bs + ((k0+kk) << 7) + 64 + (tx<<2));
            u64 bu[4] = {q0.x, q0.y, q1.x, q1.y};
            #pragma unroll
            for (int i = 0; i < 8; ++i) {
                u64 au = pack2(fcomp(a4[i], kk));
                #pragma unroll
                for (int j = 0; j < 4; ++j) ffma2(acc[i][j], au, bu[j]);
            }
        }
    }
    #pragma unroll
    for (int i = 0; i < 8; ++i) {
        int row = (ty<<3) + i;
        float* cp = C + (m0 + row)*FDIM;
        float2 p0 = unpack2(acc[i][0]), p1 = unpack2(acc[i][1]);
        float2 p2 = unpack2(acc[i][2]), p3 = unpack2(acc[i][3]);
        float4 o0 = {p0.x,p0.y,p1.x,p1.y};
        float4 o1 = {p2.x,p2.y,p3.x,p3.y};
        *(float4*)(cp + (tx<<2)) = o0;
        *(float4*)(cp + 64 + (tx<<2)) = o1;
    }
}

// ---------------- GCN aggregation: smem-staged, 2 CTAs per graph ----------------
// CTA c: graph g=c>>1, half=c&1 -> nodes base+half*64 .. +63. Full H[g] staged in smem.
__global__ void __launch_bounds__(256, 3)
agg_kernel(const float* __restrict__ h, const float* __restrict__ bias,
           const int* __restrict__ rp, const int* __restrict__ csrc,
           const float* __restrict__ cw, const float* __restrict__ dinv,
           float* __restrict__ out) {
    extern __shared__ float Hs[];
    float4* H4 = (float4*)Hs;
    int tid = threadIdx.x;
    int g = blockIdx.x >> 1;
    int half = blockIdx.x & 1;
    int base = g << 7;
    const float4* hsrc = (const float4*)(h + ((size_t)base << 7));
    #pragma unroll
    for (int i = 0; i < 16; ++i)
        H4[(i << 8) + tid] = hsrc[(i << 8) + tid];
    __syncthreads();

    int w = tid >> 5, lane = tid & 31;
    float4 bv = ((const float4*)bias)[lane];
    int mstart = (half << 6) + (w << 3);     // 8 nodes per warp
    #pragma unroll
    for (int p = 0; p < 8; ++p) {
        int m = mstart + p;
        float di = dinv[base + m];
        float w2 = di * di;
        float4 hm = H4[(m << 5) + lane];
        float4 acc;
        acc.x = fmaf(hm.x, w2, bv.x); acc.y = fmaf(hm.y, w2, bv.y);
        acc.z = fmaf(hm.z, w2, bv.z); acc.w = fmaf(hm.w, w2, bv.w);
        int e = rp[base + m], e1 = rp[base + m + 1];
        for (; e + 4 <= e1; e += 4) {
            int s0 = csrc[e] - base, s1 = csrc[e+1] - base;
            int s2 = csrc[e+2] - base, s3 = csrc[e+3] - base;
            float w0 = cw[e], w1 = cw[e+1], wv2 = cw[e+2], w3 = cw[e+3];
            float4 v0 = H4[(s0 << 5) + lane];
            float4 v1 = H4[(s1 << 5) + lane];
            float4 v2 = H4[(s2 << 5) + lane];
            float4 v3 = H4[(s3 << 5) + lane];
            acc.x = fmaf(v0.x, w0, acc.x); acc.y = fmaf(v0.y, w0, acc.y);
            acc.z = fmaf(v0.z, w0, acc.z); acc.w = fmaf(v0.w, w0, acc.w);
            acc.x = fmaf(v1.x, w1, acc.x); acc.y = fmaf(v1.y, w1, acc.y);
            acc.z = fmaf(v1.z, w1, acc.z); acc.w = fmaf(v1.w, w1, acc.w);
            acc.x = fmaf(v2.x, wv2, acc.x); acc.y = fmaf(v2.y, wv2, acc.y);
            acc.z = fmaf(v2.z, wv2, acc.z); acc.w = fmaf(v2.w, wv2, acc.w);
            acc.x = fmaf(v3.x, w3, acc.x); acc.y = fmaf(v3.y, w3, acc.y);
            acc.z = fmaf(v3.z, w3, acc.z); acc.w = fmaf(v3.w, w3, acc.w);
        }
        for (; e < e1; ++e) {
            int s = csrc[e] - base;
            float we = cw[e];
            float4 v = H4[(s << 5) + lane];
            acc.x = fmaf(v.x, we, acc.x); acc.y = fmaf(v.y, we, acc.y);
            acc.z = fmaf(v.z, we, acc.z); acc.w = fmaf(v.w, we, acc.w);
        }
        ((float4*)out)[((size_t)(base + m) << 5) + lane] = acc;
    }
}

// ---------------- fused affinity + 2-anchor Sinkhorn (R11) ----------------
__global__ void __launch_bounds__(256, 1)
aff_sink_kernel(const float* __restrict__ feat, const float* __restrict__ fc,
                const float* __restrict__ Aaff, const int* __restrict__ topk,
                float* __restrict__ sim1, float* __restrict__ sim2) {
    extern __shared__ float smf[];
    float* As = smf;                    // [128][128]
    float* Ws = smf + 128*128;          // [128][128]
    float* Bs = Ws + 128*128;           // [128][APAD]
    __shared__ float rmn[8], rmx[8], rbuf[8], bc[2];

    int tid = threadIdx.x;
    int lane = tid & 31, wid = tid >> 5;
    int which = blockIdx.x >> 8;
    int b = blockIdx.x & 255;
    const float* base = which ? fc : feat;
    const float* Xa = base + (size_t)b * LMAT;
    const float* Xb = base + HALF + (size_t)b * LMAT;
    float* P = (which ? sim2 : sim1) + (size_t)b * LMAT;

    int lr = tid >> 5, lc = (tid & 31) << 2;
    #pragma unroll
    for (int it = 0; it < 16; ++it) {
        int m = (it << 3) + lr;
        *(float4*)(As + (m << 7) + lc) = *(const float4*)(Xa + (m << 7) + lc);
        *(float4*)(Ws + (m << 7) + lc) = *(const float4*)(Aaff + (m << 7) + lc);
        float4 vb = *(const float4*)(Xb + (m << 7) + lc);
        Bs[(lc+0)*APAD + m] = vb.x; Bs[(lc+1)*APAD + m] = vb.y;
        Bs[(lc+2)*APAD + m] = vb.z; Bs[(lc+3)*APAD + m] = vb.w;
    }
    __syncthreads();
    int tx = tid & 15, ty = tid >> 4;

    // loop1: T = Xa @ Aaff
    u64 acc[8][4] = {};
    #pragma unroll 2
    for (int k0 = 0; k0 < 128; k0 += 4) {
        float4 a4[8];
        #pragma unroll
        for (int i = 0; i < 8; ++i)
            a4[i] = *(float4*)(As + ((ty<<3) + i)*128 + k0);
        #pragma unroll
        for (int kk = 0; kk < 4; ++kk) {
            ulonglong2 q0 = *(ulonglong2*)(Ws + ((k0+kk) << 7) + (tx<<2));
            ulonglong2 q1 = *(ulonglong2*)(Ws + ((k0+kk) << 7) + 64 + (tx<<2));
            u64 bu[4] = {q0.x, q0.y, q1.x, q1.y};
            #pragma unroll
            for (int i = 0; i < 8; ++i) {
                u64 au = pack2(fcomp(a4[i], kk));
                #pragma unroll
                for (int j = 0; j < 4; ++j) ffma2(acc[i][j], au, bu[j]);
            }
        }
    }
    __syncthreads();
    #pragma unroll
    for (int i = 0; i < 8; ++i) {
        int row = (ty<<3) + i;
        float2 p0 = unpack2(acc[i][0]), p1 = unpack2(acc[i][1]);
        float2 p2 = unpack2(acc[i][2]), p3 = unpack2(acc[i][3]);
        float4 o0 = {p0.x,p0.y,p1.x,p1.y};
        float4 o1 = {p2.x,p2.y,p3.x,p3.y};
        *(float4*)(As + (row << 7) + (tx<<2)) = o0;
        *(float4*)(As + (row << 7) + 64 + (tx<<2)) = o1;
    }
    __syncthreads();

    // loop2: C = T @ Xb^T
    #pragma unroll
    for (int i = 0; i < 8; ++i)
        #pragma unroll
        for (int j = 0; j < 4; ++j) acc[i][j] = 0ull;
    #pragma unroll 2
    for (int k0 = 0; k0 < 128; k0 += 4) {
        float4 a4[8];
        #pragma unroll
        for (int i = 0; i < 8; ++i)
            a4[i] = *(float4*)(As + ((ty<<3) + i)*128 + k0);
        #pragma unroll
        for (int kk = 0; kk < 4; ++kk) {
            ulonglong2 q0 = *(ulonglong2*)(Bs + (k0+kk)*APAD + (tx<<2));
            ulonglong2 q1 = *(ulonglong2*)(Bs + (k0+kk)*APAD + 64 + (tx<<2));
            u64 bu[4] = {q0.x, q0.y, q1.x, q1.y};
            #pragma unroll
            for (int i = 0; i < 8; ++i) {
                u64 au = pack2(fcomp(a4[i], kk));
                #pragma unroll
                for (int j = 0; j < 4; ++j) ffma2(acc[i][j], au, bu[j]);
            }
        }
    }

    float za[64];
    float mn = 3.4e38f, mx = -3.4e38f;
    #pragma unroll
    for (int i = 0; i < 8; ++i)
        #pragma unroll
        for (int jj = 0; jj < 4; ++jj) {
            float2 p = unpack2(acc[i][jj]);
            za[i*8 + jj*2 + 0] = p.x;
            za[i*8 + jj*2 + 1] = p.y;
            mn = fminf(mn, fminf(p.x, p.y));
            mx = fmaxf(mx, fmaxf(p.x, p.y));
        }
    #pragma unroll
    for (int off = 16; off; off >>= 1) {
        mn = fminf(mn, __shfl_xor_sync(0xffffffffu, mn, off));
        mx = fmaxf(mx, __shfl_xor_sync(0xffffffffu, mx, off));
    }
    if (lane == 0) { rmn[wid] = mn; rmx[wid] = mx; }
    __syncthreads();
    if (tid == 0) {
        float m1 = rmn[0], m2 = rmx[0];
        for (int q = 1; q < 8; ++q) { m1 = fminf(m1, rmn[q]); m2 = fmaxf(m2, rmx[q]); }
        bc[0] = m1 + m2;
    }
    __syncthreads();
    float Cc = bc[0];
    #pragma unroll
    for (int l = 0; l < 64; ++l) za[l] = fmaf(2.0f, za[l], -Cc);

    float kf = 0.5f * (float)(*topk);
    const float Lf = (float)LMAT;
    float lk = logf(kf / (Lf - kf));
    float delta = 0.0f, scale = 0.0f;
    for (int it = 0; it < SK_ITERS; ++it) {
        float T = 0.0f;
        if (it < SK_ITERS - 1) {
            #pragma unroll
            for (int l = 0; l < 64; ++l) T += fast_sigmoid(za[l] + delta);
        } else {
            #pragma unroll
            for (int l = 0; l < 64; ++l) { za[l] = fast_sigmoid(za[l] + delta); T += za[l]; }
        }
        #pragma unroll
        for (int off = 16; off; off >>= 1)
            T += __shfl_xor_sync(0xffffffffu, T, off);
        if (lane == 0) rbuf[wid] = T;
        __syncthreads();
        if (tid == 0) {
            float s = 0.0f;
            for (int q = 0; q < 8; ++q) s += rbuf[q];
            bc[1] = s;
        }
        __syncthreads();
        float Tall = bc[1];
        if (it < SK_ITERS - 1) delta += lk + logf((Lf - Tall) / Tall);
        else scale = kf / Tall;
        __syncthreads();
    }

    #pragma unroll
    for (int i = 0; i < 8; ++i) {
        int row = (ty<<3) + i;
        #pragma unroll
        for (int jj = 0; jj < 4; ++jj) {
            int c0 = ((jj < 2) ? 0 : 64) + (tx<<2) + 2*(jj & 1);
            float2 o;
            o.x = scale * za[i*8 + jj*2 + 0];
            o.y = scale * za[i*8 + jj*2 + 1];
            *(float2*)(P + (row << 7) + c0) = o;
        }
    }
}

// ---------------- graph features + scorer ----------------
__global__ void gf_kernel(const float* __restrict__ feat, const float* __restrict__ fa,
                          const float* __restrict__ fb, const float* __restrict__ fcv,
                          float* __restrict__ scores) {
    int b = blockIdx.x;
    int tid = threadIdx.x;
    int job = tid >> 5, lane = tid & 31;
    int buf = job & 3;
    const float* p = (buf==0?feat:buf==1?fa:buf==2?fb:fcv);
    if (job < 4) {
        const float4* p4 = (const float4*)(p + (((size_t)b*NNODE) << 7)) + lane;
        float4 s = {0,0,0,0};
        #pragma unroll 4
        for (int n = 0; n < NNODE; ++n) {
            float4 v = p4[n << 5];
            s.x += v.x; s.y += v.y; s.z += v.z; s.w += v.w;
        }
        ((float4*)(scores + b*1024 + buf*128))[lane] = s;
    } else {
        const float4* p4 = (const float4*)(p + HALF + (((size_t)b*NNODE) << 7)) + lane;
        float4 m = {-3.4e38f,-3.4e38f,-3.4e38f,-3.4e38f};
        #pragma unroll 4
        for (int n = 0; n < NNODE; ++n) {
            float4 v = p4[n << 5];
            m.x = fmaxf(m.x, v.x); m.y = fmaxf(m.y, v.y);
            m.z = fmaxf(m.z, v.z); m.w = fmaxf(m.w, v.w);
        }
        ((float4*)(scores + b*1024 + 512 + buf*128))[lane] = m;
    }
}

__global__ void score_kernel(const float* __restrict__ scores,
                             const float* __restrict__ W1, const float* __restrict__ b1,
                             const float* __restrict__ W2, const float* __restrict__ b2,
                             float* __restrict__ ged) {
    int b = blockIdx.x;
    int j = threadIdx.x;
    __shared__ float sv[1024];
    __shared__ float rr[2];
    for (int i = j; i < 1024; i += 64) sv[i] = scores[b*1024 + i];
    __syncthreads();
    float acc = b1[j];
    #pragma unroll 8
    for (int i = 0; i < 1024; ++i)
        acc = fmaf(sv[i], W1[i*64 + j], acc);
    float pv = fmaxf(acc, 0.0f) * W2[j];
    #pragma unroll
    for (int off = 16; off; off >>= 1)
        pv += __shfl_xor_sync(0xffffffffu, pv, off);
    if ((j & 31) == 0) rr[j >> 5] = pv;
    __syncthreads();
    if (j == 0) {
        float v = rr[0] + rr[1] + b2[0];
        ged[b] = 1.0f / (1.0f + expf(-v));
    }
}

// ---------------- streams/events (created once, on the uncaptured first call) ----------------
static cudaStream_t g_s1 = nullptr;
static cudaEvent_t g_evFork = nullptr, g_evCsr = nullptr, g_evFc = nullptr, g_evTail = nullptr;

extern "C" void kernel_launch(void* const* d_in, const int* in_sizes, int n_in,
                              void* d_out, int out_size) {
    const float* x1    = (const float*)d_in[0];
    const int*   cent1 = (const int*)d_in[1];
    const float* rw1   = (const float*)d_in[2];
    const int*   src1  = (const int*)d_in[3];
    const int*   dst1  = (const int*)d_in[4];
    const float* x2    = (const float*)d_in[5];
    const int*   cent2 = (const int*)d_in[6];
    const float* rw2   = (const float*)d_in[7];
    const int*   src2  = (const int*)d_in[8];
    const int*   dst2  = (const int*)d_in[9];
    const float* emb   = (const float*)d_in[10];
    const float* initW = (const float*)d_in[11];
    const float* initb = (const float*)d_in[12];
    const float* W1    = (const float*)d_in[13];
    const float* b1    = (const float*)d_in[14];
    const float* W2    = (const float*)d_in[15];
    const float* b2    = (const float*)d_in[16];
    const float* W3    = (const float*)d_in[17];
    const float* b3    = (const float*)d_in[18];
    const float* Aaff  = (const float*)d_in[19];
    const float* scW1  = (const float*)d_in[20];
    const float* scb1  = (const float*)d_in[21];
    const float* scW2  = (const float*)d_in[22];
    const float* scb2  = (const float*)d_in[23];
    const int*   topk  = (const int*)d_in[24];

    Scratch* S = nullptr;
    cudaGetSymbolAddress((void**)&S, g_scratch);

    float* out  = (float*)d_out;
    float* ged  = out;
    float* sim1 = out + BATCH;
    float* sim2 = out + BATCH + (size_t)BATCH * LMAT;

    if (g_s1 == nullptr) {
        cudaStreamCreateWithFlags(&g_s1, cudaStreamNonBlocking);
        cudaEventCreateWithFlags(&g_evFork, cudaEventDisableTiming);
        cudaEventCreateWithFlags(&g_evCsr,  cudaEventDisableTiming);
        cudaEventCreateWithFlags(&g_evFc,   cudaEventDisableTiming);
        cudaEventCreateWithFlags(&g_evTail, cudaEventDisableTiming);
    }
    cudaStream_t s0 = 0, s1 = g_s1;

    cudaFuncSetAttribute(gemm_aw_kernel,  cudaFuncAttributeMaxDynamicSharedMemorySize, SMEM_G);
    cudaFuncSetAttribute(agg_kernel,      cudaFuncAttributeMaxDynamicSharedMemorySize, SMEM_AGG);
    cudaFuncSetAttribute(aff_sink_kernel, cudaFuncAttributeMaxDynamicSharedMemorySize, SMEM_FUSE);

    // fork: s1 builds CSR while s0 does init features + GEMM #1
    cudaEventRecord(g_evFork, s0);
    cudaStreamWaitEvent(s1, g_evFork, 0);

    init_feat_kernel<<<NTOT, 256, 0, s0>>>(x1, cent1, rw1, x2, cent2, rw2,
                                           emb, initW, initb, S->feat);            // 1 (s0)
    zero_kernel<<<64, 256, 0, s1>>>(S->deg, S->fill);                              // 2 (s1)
    count_kernel<<<NEDGE2/256, 256, 0, s1>>>(dst1, dst2, S->deg);                  // 3 (s1)
    gemm_aw_kernel<<<NTOT2/64, 128, SMEM_G, s0>>>(S->feat, W1, S->htmp, 0);        // 4 (s0) <- profiled
    scan_block_kernel<<<64, 1024, 0, s1>>>(S->deg, S->rp, S->dinv, S->bsum);       // 5 (s1)
    scan_add_kernel<<<64, 1024, 0, s1>>>(S->rp, S->bsum);                          // 6 (s1)
    scatter_kernel<<<NEDGE2/256, 256, 0, s1>>>(src1, dst1, src2, dst2, S->rp,
                                               S->fill, S->dinv, S->csrc, S->cw);  // 7 (s1)
    cudaEventRecord(g_evCsr, s1);
    cudaStreamWaitEvent(s0, g_evCsr, 0);   // join: aggregation needs CSR

    agg_kernel<<<1024, 256, SMEM_AGG, s0>>>(S->htmp, b1, S->rp, S->csrc, S->cw, S->dinv, S->fa);
    gemm_aw_kernel<<<NTOT2/64, 128, SMEM_G, s0>>>(S->fa, W2, S->htmp, 1);
    agg_kernel<<<1024, 256, SMEM_AGG, s0>>>(S->htmp, b2, S->rp, S->csrc, S->cw, S->dinv, S->fb);
    gemm_aw_kernel<<<NTOT2/64, 128, SMEM_G, s0>>>(S->fb, W3, S->htmp, 1);
    agg_kernel<<<1024, 256, SMEM_AGG, s0>>>(S->htmp, b3, S->rp, S->csrc, S->cw, S->dinv, S->fc);

    // fork: gf + scorer on s1 concurrent with aff_sink on s0
    cudaEventRecord(g_evFc, s0);
    cudaStreamWaitEvent(s1, g_evFc, 0);
    aff_sink_kernel<<<2*BATCH, 256, SMEM_FUSE, s0>>>(S->feat, S->fc, Aaff, topk, sim1, sim2);
    gf_kernel<<<BATCH, 256, 0, s1>>>(S->feat, S->fa, S->fb, S->fc, S->scores);
    score_kernel<<<BATCH, 64, 0, s1>>>(S->scores, scW1, scb1, scW2, scb2, ged);
    cudaEventRecord(g_evTail, s1);
    cudaStreamWaitEvent(s0, g_evTail, 0);  // join so the graph's leaf is on s0
}

// round 14
// speedup vs baseline: 1.0571x; 1.0284x over previous
#include <cuda_runtime.h>
#include <math.h>

#define BATCH   256
#define NNODE   128
#define NTOT    32768
#define NTOT2   65536
#define NEDGE   262144
#define NEDGE2  524288
#define FDIM    128
#define HALF    (NTOT*FDIM)
#define LDIMS   61
#define LMAT    16384
#define SK_ITERS 6
#define APAD    132
#define SMEM_G    ((64*128 + 128*128)*4)                    // 96KB (R11 proven)
#define SMEM_FUSE ((128*128 + 128*128 + 128*APAD)*4)

typedef unsigned long long u64;

struct Scratch {
    float feat[NTOT2*FDIM];
    float fa[NTOT2*FDIM];
    float fb[NTOT2*FDIM];
    float fc[NTOT2*FDIM];
    float htmp[NTOT2*FDIM];
    float cw[NEDGE2];
    float dinv[NTOT2];
    float scores[BATCH*1024];
    int csrc[NEDGE2];
    int deg[NTOT2];
    int fill[NTOT2];
    int rp[NTOT2+1];
    int bsum[64];
};
__device__ Scratch g_scratch;

// ---------------- f32x2 packed FMA helpers ----------------
__device__ __forceinline__ u64 pack2(float v) {
    u64 r; asm("mov.b64 %0, {%1, %1};" : "=l"(r) : "f"(v)); return r;
}
__device__ __forceinline__ void ffma2(u64& d, u64 a, u64 b) {
    asm("fma.rn.f32x2 %0, %1, %2, %3;" : "=l"(d) : "l"(a), "l"(b), "l"(d));
}
__device__ __forceinline__ float2 unpack2(u64 v) {
    float2 f; asm("mov.b64 {%0, %1}, %2;" : "=f"(f.x), "=f"(f.y) : "l"(v)); return f;
}
__device__ __forceinline__ float fcomp(float4 v, int kk) {
    return (kk==0) ? v.x : (kk==1) ? v.y : (kk==2) ? v.z : v.w;
}

// FMA-pipe sigmoid (no MUFU)
__device__ __forceinline__ float fast_sigmoid(float z) {
    float az = fminf(fabsf(z), 80.0f);
    float t = az * 1.4426950408889634f;
    float n = rintf(t);
    float w = -(t - n) * 0.6931471805599453f;
    float p = fmaf(w, 0.00833333377f, 0.0416666679f);
    p = fmaf(w, p, 0.16666667f);
    p = fmaf(w, p, 0.5f);
    p = fmaf(w, p, 1.0f);
    p = fmaf(w, p, 1.0f);
    float e = p * __int_as_float((127 - (int)n) << 23);
    float d = 1.0f + e;
    float y = fmaf(-0.5f, d, 1.45711f);
    y = y * fmaf(-d, y, 2.0f);
    y = y * fmaf(-d, y, 2.0f);
    y = y * fmaf(-d, y, 2.0f);
    return (z >= 0.0f) ? y : e * y;
}

// ---------------- CSR build ----------------
__global__ void zero_kernel(int* __restrict__ deg, int* __restrict__ fill) {
    int i = blockIdx.x*blockDim.x + threadIdx.x;
    int4 z = {0,0,0,0};
    ((int4*)deg)[i] = z;
    ((int4*)fill)[i] = z;
}
__global__ void count_kernel(const int* __restrict__ dst1, const int* __restrict__ dst2,
                             int* __restrict__ deg) {
    int e = blockIdx.x*blockDim.x + threadIdx.x;
    if (e < NEDGE) atomicAdd(&deg[dst1[e]], 1);
    else if (e < NEDGE2) atomicAdd(&deg[dst2[e - NEDGE] + NTOT], 1);
}
__global__ void scan_block_kernel(const int* __restrict__ deg, int* __restrict__ rp,
                                  float* __restrict__ dinv, int* __restrict__ bsum) {
    __shared__ int ws[32];
    int tid = threadIdx.x, lane = tid & 31, wid = tid >> 5;
    int gi = blockIdx.x*1024 + tid;
    int v = deg[gi];
    dinv[gi] = rsqrtf((float)(v + 1));
    int x = v;
    #pragma unroll
    for (int off = 1; off < 32; off <<= 1) {
        int t = __shfl_up_sync(0xffffffffu, x, off);
        if (lane >= off) x += t;
    }
    if (lane == 31) ws[wid] = x;
    __syncthreads();
    if (wid == 0) {
        int y = ws[lane];
        #pragma unroll
        for (int off = 1; off < 32; off <<= 1) {
            int t = __shfl_up_sync(0xffffffffu, y, off);
            if (lane >= off) y += t;
        }
        ws[lane] = y;
    }
    __syncthreads();
    int woff = (wid > 0) ? ws[wid-1] : 0;
    rp[gi] = woff + x - v;
    if (tid == 1023) bsum[blockIdx.x] = woff + x;
}
__global__ void scan_add_kernel(int* __restrict__ rp, const int* __restrict__ bsum) {
    __shared__ int off_s;
    if (threadIdx.x == 0) {
        int acc = 0;
        for (int i = 0; i < blockIdx.x; ++i) acc += bsum[i];
        off_s = acc;
    }
    __syncthreads();
    int gi = blockIdx.x*1024 + threadIdx.x;
    rp[gi] += off_s;
    if (gi == 0) rp[NTOT2] = NEDGE2;
}
__global__ void scatter_kernel(const int* __restrict__ src1, const int* __restrict__ dst1,
                               const int* __restrict__ src2, const int* __restrict__ dst2,
                               const int* __restrict__ rp, int* __restrict__ fill,
                               const float* __restrict__ dinv,
                               int* __restrict__ csrc, float* __restrict__ cw) {
    int e = blockIdx.x*blockDim.x + threadIdx.x;
    if (e >= NEDGE2) return;
    int s, d;
    if (e < NEDGE) { s = src1[e]; d = dst1[e]; }
    else { s = src2[e - NEDGE] + NTOT; d = dst2[e - NEDGE] + NTOT; }
    int pos = rp[d] + atomicAdd(&fill[d], 1);
    csrc[pos] = s;
    cw[pos] = dinv[s] * dinv[d];
}

// ---------------- initial features ----------------
__global__ void init_feat_kernel(const float* __restrict__ x1, const int* __restrict__ c1,
                                 const float* __restrict__ rw1,
                                 const float* __restrict__ x2, const int* __restrict__ c2,
                                 const float* __restrict__ rw2,
                                 const float* __restrict__ emb,
                                 const float* __restrict__ W, const float* __restrict__ bias,
                                 float* __restrict__ out) {
    int which = blockIdx.x >> 14;
    int bi = blockIdx.x & 16383;
    const float* x  = which ? x2 : x1;
    const int*   ce = which ? c2 : c1;
    const float* rw = which ? rw2 : rw1;
    int half = threadIdx.x >> 7;
    int f = threadIdx.x & 127;
    int node = bi*2 + half;
    __shared__ float a[2][LDIMS];
    if (f < 29)      a[half][f] = x[node*29 + f];
    else if (f < 45) a[half][f] = emb[ce[node]*16 + (f-29)];
    else if (f < 61) a[half][f] = rw[node*16 + (f-45)];
    __syncthreads();
    float acc = bias[f];
    #pragma unroll
    for (int c = 0; c < LDIMS; ++c)
        acc = fmaf(a[half][c], W[c*FDIM + f], acc);
    out[((size_t)(which*NTOT + node) << 7) + f] = fmaxf(acc, 0.0f);
}

// ---------------- GEMM C[64-tile,128] = op(A) @ W, 128 thr, 8x8 microtile (R11) ----------------
__global__ void __launch_bounds__(128, 2)
gemm_aw_kernel(const float* __restrict__ A, const float* __restrict__ W,
               float* __restrict__ C, int relu_a) {
    extern __shared__ float sm[];
    float* As = sm;               // [64][128] row-major
    float* Bs = sm + 64*128;      // [128][128]
    int tid = threadIdx.x;
    size_t m0 = (size_t)blockIdx.x * 64;

    {
        int r = tid >> 5, c4 = (tid & 31) << 2;
        #pragma unroll
        for (int it = 0; it < 16; ++it) {
            int m = (it << 2) + r;
            float4 v = *(const float4*)(A + (m0 + m)*FDIM + c4);
            if (relu_a) { v.x=fmaxf(v.x,0.f); v.y=fmaxf(v.y,0.f); v.z=fmaxf(v.z,0.f); v.w=fmaxf(v.w,0.f); }
            *(float4*)(As + (m << 7) + c4) = v;
        }
        #pragma unroll
        for (int it = 0; it < 32; ++it) {
            int m = (it << 2) + r;
            *(float4*)(Bs + (m << 7) + c4) = *(const float4*)(W + m*FDIM + c4);
        }
    }
    __syncthreads();

    int tx = tid & 15, ty = tid >> 4;      // ty 0..7 -> rows ty*8..+7
    u64 acc[8][4] = {};
    #pragma unroll 2
    for (int k0 = 0; k0 < 128; k0 += 4) {
        float4 a4[8];
        #pragma unroll
        for (int i = 0; i < 8; ++i)
            a4[i] = *(float4*)(As + ((ty<<3) + i)*128 + k0);   // broadcast
        #pragma unroll
        for (int kk = 0; kk < 4; ++kk) {
            ulonglong2 q0 = *(ulonglong2*)(Bs + ((k0+kk) << 7) + (tx<<2));
            ulonglong2 q1 = *(ulonglong2*)(Bs + ((k0+kk) << 7) + 64 + (tx<<2));
            u64 bu[4] = {q0.x, q0.y, q1.x, q1.y};
            #pragma unroll
            for (int i = 0; i < 8; ++i) {
                u64 au = pack2(fcomp(a4[i], kk));
                #pragma unroll
                for (int j = 0; j < 4; ++j) ffma2(acc[i][j], au, bu[j]);
            }
        }
    }
    #pragma unroll
    for (int i = 0; i < 8; ++i) {
        int row = (ty<<3) + i;
        float* cp = C + (m0 + row)*FDIM;
        float2 p0 = unpack2(acc[i][0]), p1 = unpack2(acc[i][1]);
        float2 p2 = unpack2(acc[i][2]), p3 = unpack2(acc[i][3]);
        float4 o0 = {p0.x,p0.y,p1.x,p1.y};
        float4 o1 = {p2.x,p2.y,p3.x,p3.y};
        *(float4*)(cp + (tx<<2)) = o0;
        *(float4*)(cp + 64 + (tx<<2)) = o1;
    }
}

// ---------------- GCN aggregation: warp per node, float4 per lane (R11 proven) ----------------
__global__ void agg_kernel(const float* __restrict__ h, const float* __restrict__ bias,
                           const int* __restrict__ rp, const int* __restrict__ csrc,
                           const float* __restrict__ cw, const float* __restrict__ dinv,
                           float* __restrict__ out) {
    int n = (blockIdx.x << 3) + (threadIdx.x >> 5);
    int lane = threadIdx.x & 31;
    const float4* h4 = (const float4*)h;
    float di = dinv[n];
    float4 bv = ((const float4*)bias)[lane];
    float4 hv = h4[((size_t)n << 5) + lane];
    float w2 = di*di;
    float4 acc;
    acc.x = fmaf(hv.x, w2, bv.x); acc.y = fmaf(hv.y, w2, bv.y);
    acc.z = fmaf(hv.z, w2, bv.z); acc.w = fmaf(hv.w, w2, bv.w);
    int e = rp[n], e1 = rp[n+1];
    for (; e + 4 <= e1; e += 4) {
        int s0 = csrc[e], s1 = csrc[e+1], s2 = csrc[e+2], s3 = csrc[e+3];
        float w0 = cw[e], w1 = cw[e+1], wv2 = cw[e+2], w3 = cw[e+3];
        float4 v0 = h4[((size_t)s0 << 5) + lane];
        float4 v1 = h4[((size_t)s1 << 5) + lane];
        float4 v2 = h4[((size_t)s2 << 5) + lane];
        float4 v3 = h4[((size_t)s3 << 5) + lane];
        acc.x = fmaf(v0.x, w0, acc.x); acc.y = fmaf(v0.y, w0, acc.y);
        acc.z = fmaf(v0.z, w0, acc.z); acc.w = fmaf(v0.w, w0, acc.w);
        acc.x = fmaf(v1.x, w1, acc.x); acc.y = fmaf(v1.y, w1, acc.y);
        acc.z = fmaf(v1.z, w1, acc.z); acc.w = fmaf(v1.w, w1, acc.w);
        acc.x = fmaf(v2.x, wv2, acc.x); acc.y = fmaf(v2.y, wv2, acc.y);
        acc.z = fmaf(v2.z, wv2, acc.z); acc.w = fmaf(v2.w, wv2, acc.w);
        acc.x = fmaf(v3.x, w3, acc.x); acc.y = fmaf(v3.y, w3, acc.y);
        acc.z = fmaf(v3.z, w3, acc.z); acc.w = fmaf(v3.w, w3, acc.w);
    }
    for (; e < e1; ++e) {
        float w = cw[e];
        float4 v = h4[((size_t)csrc[e] << 5) + lane];
        acc.x = fmaf(v.x, w, acc.x); acc.y = fmaf(v.y, w, acc.y);
        acc.z = fmaf(v.z, w, acc.z); acc.w = fmaf(v.w, w, acc.w);
    }
    ((float4*)out)[((size_t)n << 5) + lane] = acc;
}

// ---------------- fused affinity + 2-anchor Sinkhorn: 512 threads, 8x4 microtile ----------------
// warp w owns rows w*8..+7 (A-reads broadcast); lane owns cols 4l..4l+3.
__global__ void __launch_bounds__(512, 1)
aff_sink_kernel(const float* __restrict__ feat, const float* __restrict__ fc,
                const float* __restrict__ Aaff, const int* __restrict__ topk,
                float* __restrict__ sim1, float* __restrict__ sim2) {
    extern __shared__ float smf[];
    float* As = smf;                    // [128][128] Xa then T
    float* Ws = smf + 128*128;          // [128][128] Aaff
    float* Bs = Ws + 128*128;           // [128][APAD] Xb^T
    __shared__ float rmn[16], rmx[16], rbuf[16], bc[2];

    int tid = threadIdx.x;
    int lane = tid & 31, wid = tid >> 5;      // wid 0..15
    int which = blockIdx.x >> 8;
    int b = blockIdx.x & 255;
    const float* base = which ? fc : feat;
    const float* Xa = base + (size_t)b * LMAT;
    const float* Xb = base + HALF + (size_t)b * LMAT;
    float* P = (which ? sim2 : sim1) + (size_t)b * LMAT;

    {
        int lr = tid >> 5, lc = (tid & 31) << 2;
        #pragma unroll
        for (int it = 0; it < 8; ++it) {
            int m = (it << 4) + lr;
            *(float4*)(As + (m << 7) + lc) = *(const float4*)(Xa + (m << 7) + lc);
            *(float4*)(Ws + (m << 7) + lc) = *(const float4*)(Aaff + (m << 7) + lc);
            float4 vb = *(const float4*)(Xb + (m << 7) + lc);
            Bs[(lc+0)*APAD + m] = vb.x; Bs[(lc+1)*APAD + m] = vb.y;
            Bs[(lc+2)*APAD + m] = vb.z; Bs[(lc+3)*APAD + m] = vb.w;
        }
    }
    __syncthreads();
    int c4 = lane << 2;

    // loop1: T = Xa @ Aaff   (acc 8 rows x 4 cols)
    u64 acc[8][2] = {};
    #pragma unroll 2
    for (int k0 = 0; k0 < 128; k0 += 4) {
        float4 a4[8];
        #pragma unroll
        for (int i = 0; i < 8; ++i)
            a4[i] = *(float4*)(As + ((wid<<3) + i)*128 + k0);   // warp broadcast
        #pragma unroll
        for (int kk = 0; kk < 4; ++kk) {
            ulonglong2 q = *(ulonglong2*)(Ws + ((k0+kk) << 7) + c4);
            #pragma unroll
            for (int i = 0; i < 8; ++i) {
                u64 au = pack2(fcomp(a4[i], kk));
                ffma2(acc[i][0], au, q.x);
                ffma2(acc[i][1], au, q.y);
            }
        }
    }
    __syncthreads();
    #pragma unroll
    for (int i = 0; i < 8; ++i) {
        int row = (wid<<3) + i;
        float2 p0 = unpack2(acc[i][0]), p1 = unpack2(acc[i][1]);
        float4 o = {p0.x, p0.y, p1.x, p1.y};
        *(float4*)(As + (row << 7) + c4) = o;
    }
    __syncthreads();

    // loop2: C = T @ Xb^T
    #pragma unroll
    for (int i = 0; i < 8; ++i) { acc[i][0] = 0ull; acc[i][1] = 0ull; }
    #pragma unroll 2
    for (int k0 = 0; k0 < 128; k0 += 4) {
        float4 a4[8];
        #pragma unroll
        for (int i = 0; i < 8; ++i)
            a4[i] = *(float4*)(As + ((wid<<3) + i)*128 + k0);
        #pragma unroll
        for (int kk = 0; kk < 4; ++kk) {
            ulonglong2 q = *(ulonglong2*)(Bs + (k0+kk)*APAD + c4);
            #pragma unroll
            for (int i = 0; i < 8; ++i) {
                u64 au = pack2(fcomp(a4[i], kk));
                ffma2(acc[i][0], au, q.x);
                ffma2(acc[i][1], au, q.y);
            }
        }
    }

    float za[32];
    float mn = 3.4e38f, mx = -3.4e38f;
    #pragma unroll
    for (int i = 0; i < 8; ++i) {
        float2 p0 = unpack2(acc[i][0]), p1 = unpack2(acc[i][1]);
        za[i*4 + 0] = p0.x; za[i*4 + 1] = p0.y;
        za[i*4 + 2] = p1.x; za[i*4 + 3] = p1.y;
        mn = fminf(mn, fminf(fminf(p0.x, p0.y), fminf(p1.x, p1.y)));
        mx = fmaxf(mx, fmaxf(fmaxf(p0.x, p0.y), fmaxf(p1.x, p1.y)));
    }
    #pragma unroll
    for (int off = 16; off; off >>= 1) {
        mn = fminf(mn, __shfl_xor_sync(0xffffffffu, mn, off));
        mx = fmaxf(mx, __shfl_xor_sync(0xffffffffu, mx, off));
    }
    if (lane == 0) { rmn[wid] = mn; rmx[wid] = mx; }
    __syncthreads();
    if (tid == 0) {
        float m1 = rmn[0], m2 = rmx[0];
        for (int q = 1; q < 16; ++q) { m1 = fminf(m1, rmn[q]); m2 = fmaxf(m2, rmx[q]); }
        bc[0] = m1 + m2;
    }
    __syncthreads();
    float Cc = bc[0];
    #pragma unroll
    for (int l = 0; l < 32; ++l) za[l] = fmaf(2.0f, za[l], -Cc);

    float kf = 0.5f * (float)(*topk);
    const float Lf = (float)LMAT;
    float lk = logf(kf / (Lf - kf));
    float delta = 0.0f, scale = 0.0f;
    for (int it = 0; it < SK_ITERS; ++it) {
        float T = 0.0f;
        if (it < SK_ITERS - 1) {
            #pragma unroll
            for (int l = 0; l < 32; ++l) T += fast_sigmoid(za[l] + delta);
        } else {
            #pragma unroll
            for (int l = 0; l < 32; ++l) { za[l] = fast_sigmoid(za[l] + delta); T += za[l]; }
        }
        #pragma unroll
        for (int off = 16; off; off >>= 1)
            T += __shfl_xor_sync(0xffffffffu, T, off);
        if (lane == 0) rbuf[wid] = T;
        __syncthreads();
        if (tid == 0) {
            float s = 0.0f;
            for (int q = 0; q < 16; ++q) s += rbuf[q];
            bc[1] = s;
        }
        __syncthreads();
        float Tall = bc[1];
        if (it < SK_ITERS - 1) delta += lk + logf((Lf - Tall) / Tall);
        else scale = kf / Tall;
        __syncthreads();
    }

    #pragma unroll
    for (int i = 0; i < 8; ++i) {
        int row = (wid<<3) + i;
        float4 o = {scale * za[i*4 + 0], scale * za[i*4 + 1],
                    scale * za[i*4 + 2], scale * za[i*4 + 3]};
        *(float4*)(P + (row << 7) + c4) = o;
    }
}

// ---------------- graph features + scorer ----------------
__global__ void gf_kernel(const float* __restrict__ feat, const float* __restrict__ fa,
                          const float* __restrict__ fb, const float* __restrict__ fcv,
                          float* __restrict__ scores) {
    int b = blockIdx.x;
    int tid = threadIdx.x;
    int job = tid >> 5, lane = tid & 31;
    int buf = job & 3;
    const float* p = (buf==0?feat:buf==1?fa:buf==2?fb:fcv);
    if (job < 4) {
        const float4* p4 = (const float4*)(p + (((size_t)b*NNODE) << 7)) + lane;
        float4 s = {0,0,0,0};
        #pragma unroll 4
        for (int n = 0; n < NNODE; ++n) {
            float4 v = p4[n << 5];
            s.x += v.x; s.y += v.y; s.z += v.z; s.w += v.w;
        }
        ((float4*)(scores + b*1024 + buf*128))[lane] = s;
    } else {
        const float4* p4 = (const float4*)(p + HALF + (((size_t)b*NNODE) << 7)) + lane;
        float4 m = {-3.4e38f,-3.4e38f,-3.4e38f,-3.4e38f};
        #pragma unroll 4
        for (int n = 0; n < NNODE; ++n) {
            float4 v = p4[n << 5];
            m.x = fmaxf(m.x, v.x); m.y = fmaxf(m.y, v.y);
            m.z = fmaxf(m.z, v.z); m.w = fmaxf(m.w, v.w);
        }
        ((float4*)(scores + b*1024 + 512 + buf*128))[lane] = m;
    }
}

__global__ void score_kernel(const float* __restrict__ scores,
                             const float* __restrict__ W1, const float* __restrict__ b1,
                             const float* __restrict__ W2, const float* __restrict__ b2,
                             float* __restrict__ ged) {
    int b = blockIdx.x;
    int j = threadIdx.x;
    __shared__ float sv[1024];
    __shared__ float rr[2];
    for (int i = j; i < 1024; i += 64) sv[i] = scores[b*1024 + i];
    __syncthreads();
    float acc = b1[j];
    #pragma unroll 8
    for (int i = 0; i < 1024; ++i)
        acc = fmaf(sv[i], W1[i*64 + j], acc);
    float pv = fmaxf(acc, 0.0f) * W2[j];
    #pragma unroll
    for (int off = 16; off; off >>= 1)
        pv += __shfl_xor_sync(0xffffffffu, pv, off);
    if ((j & 31) == 0) rr[j >> 5] = pv;
    __syncthreads();
    if (j == 0) {
        float v = rr[0] + rr[1] + b2[0];
        ged[b] = 1.0f / (1.0f + expf(-v));
    }
}

// ---------------- streams/events (created once, on the uncaptured first call) ----------------
static cudaStream_t g_s1 = nullptr;
static cudaEvent_t g_evFork = nullptr, g_evCsr = nullptr, g_evFc = nullptr, g_evTail = nullptr;

extern "C" void kernel_launch(void* const* d_in, const int* in_sizes, int n_in,
                              void* d_out, int out_size) {
    const float* x1    = (const float*)d_in[0];
    const int*   cent1 = (const int*)d_in[1];
    const float* rw1   = (const float*)d_in[2];
    const int*   src1  = (const int*)d_in[3];
    const int*   dst1  = (const int*)d_in[4];
    const float* x2    = (const float*)d_in[5];
    const int*   cent2 = (const int*)d_in[6];
    const float* rw2   = (const float*)d_in[7];
    const int*   src2  = (const int*)d_in[8];
    const int*   dst2  = (const int*)d_in[9];
    const float* emb   = (const float*)d_in[10];
    const float* initW = (const float*)d_in[11];
    const float* initb = (const float*)d_in[12];
    const float* W1    = (const float*)d_in[13];
    const float* b1    = (const float*)d_in[14];
    const float* W2    = (const float*)d_in[15];
    const float* b2    = (const float*)d_in[16];
    const float* W3    = (const float*)d_in[17];
    const float* b3    = (const float*)d_in[18];
    const float* Aaff  = (const float*)d_in[19];
    const float* scW1  = (const float*)d_in[20];
    const float* scb1  = (const float*)d_in[21];
    const float* scW2  = (const float*)d_in[22];
    const float* scb2  = (const float*)d_in[23];
    const int*   topk  = (const int*)d_in[24];

    Scratch* S = nullptr;
    cudaGetSymbolAddress((void**)&S, g_scratch);

    float* out  = (float*)d_out;
    float* ged  = out;
    float* sim1 = out + BATCH;
    float* sim2 = out + BATCH + (size_t)BATCH * LMAT;

    if (g_s1 == nullptr) {
        cudaStreamCreateWithFlags(&g_s1, cudaStreamNonBlocking);
        cudaEventCreateWithFlags(&g_evFork, cudaEventDisableTiming);
        cudaEventCreateWithFlags(&g_evCsr,  cudaEventDisableTiming);
        cudaEventCreateWithFlags(&g_evFc,   cudaEventDisableTiming);
        cudaEventCreateWithFlags(&g_evTail, cudaEventDisableTiming);
    }
    cudaStream_t s0 = 0, s1 = g_s1;

    cudaFuncSetAttribute(gemm_aw_kernel,  cudaFuncAttributeMaxDynamicSharedMemorySize, SMEM_G);
    cudaFuncSetAttribute(aff_sink_kernel, cudaFuncAttributeMaxDynamicSharedMemorySize, SMEM_FUSE);

    // fork: s1 builds CSR while s0 does init features + GEMM #1
    cudaEventRecord(g_evFork, s0);
    cudaStreamWaitEvent(s1, g_evFork, 0);

    init_feat_kernel<<<NTOT, 256, 0, s0>>>(x1, cent1, rw1, x2, cent2, rw2,
                                           emb, initW, initb, S->feat);            // 1 (s0)
    zero_kernel<<<64, 256, 0, s1>>>(S->deg, S->fill);                              // 2 (s1)
    count_kernel<<<NEDGE2/256, 256, 0, s1>>>(dst1, dst2, S->deg);                  // 3 (s1)
    gemm_aw_kernel<<<NTOT2/64, 128, SMEM_G, s0>>>(S->feat, W1, S->htmp, 0);        // 4 (s0) <- profiled
    scan_block_kernel<<<64, 1024, 0, s1>>>(S->deg, S->rp, S->dinv, S->bsum);       // 5 (s1)
    scan_add_kernel<<<64, 1024, 0, s1>>>(S->rp, S->bsum);                          // 6 (s1)
    scatter_kernel<<<NEDGE2/256, 256, 0, s1>>>(src1, dst1, src2, dst2, S->rp,
                                               S->fill, S->dinv, S->csrc, S->cw);  // 7 (s1)
    cudaEventRecord(g_evCsr, s1);
    cudaStreamWaitEvent(s0, g_evCsr, 0);   // join: aggregation needs CSR

    agg_kernel<<<NTOT2/8, 256, 0, s0>>>(S->htmp, b1, S->rp, S->csrc, S->cw, S->dinv, S->fa);
    gemm_aw_kernel<<<NTOT2/64, 128, SMEM_G, s0>>>(S->fa, W2, S->htmp, 1);
    agg_kernel<<<NTOT2/8, 256, 0, s0>>>(S->htmp, b2, S->rp, S->csrc, S->cw, S->dinv, S->fb);
    gemm_aw_kernel<<<NTOT2/64, 128, SMEM_G, s0>>>(S->fb, W3, S->htmp, 1);
    agg_kernel<<<NTOT2/8, 256, 0, s0>>>(S->htmp, b3, S->rp, S->csrc, S->cw, S->dinv, S->fc);

    // fork: gf + scorer on s1 concurrent with aff_sink on s0
    cudaEventRecord(g_evFc, s0);
    cudaStreamWaitEvent(s1, g_evFc, 0);
    aff_sink_kernel<<<2*BATCH, 512, SMEM_FUSE, s0>>>(S->feat, S->fc, Aaff, topk, sim1, sim2);
    gf_kernel<<<BATCH, 256, 0, s1>>>(S->feat, S->fa, S->fb, S->fc, S->scores);
    score_kernel<<<BATCH, 64, 0, s1>>>(S->scores, scW1, scb1, scW2, scb2, ged);
    cudaEventRecord(g_evTail, s1);
    cudaStreamWaitEvent(s0, g_evTail, 0);  // join so the graph's leaf is on s0
}

// round 15
// speedup vs baseline: 1.0881x; 1.0293x over previous
#include <cuda_runtime.h>
#include <math.h>

#define BATCH   256
#define NNODE   128
#define NTOT    32768
#define NTOT2   65536
#define NEDGE   262144
#define NEDGE2  524288
#define FDIM    128
#define HALF    (NTOT*FDIM)
#define LDIMS   61
#define LMAT    16384
#define SK_ITERS 6
#define APAD    132
#define SMEM_G    ((64*128 + 128*128)*4)
#define SMEM_FUSE ((128*128 + 128*128 + 128*APAD)*4)

typedef unsigned long long u64;

struct Scratch {
    float feat[NTOT2*FDIM];
    float fa[NTOT2*FDIM];
    float fb[NTOT2*FDIM];
    float fc[NTOT2*FDIM];
    float htmp[NTOT2*FDIM];
    float cw[NEDGE2];
    float dinv[NTOT2];
    float scores[BATCH*1024];
    int csrc[NEDGE2];
    int deg[NTOT2];
    int fill[NTOT2];
    int rp[NTOT2+1];
    int bsum[64];
};
__device__ Scratch g_scratch;

// ---------------- f32x2 packed FMA helpers ----------------
__device__ __forceinline__ u64 pack2(float v) {
    u64 r; asm("mov.b64 %0, {%1, %1};" : "=l"(r) : "f"(v)); return r;
}
__device__ __forceinline__ void ffma2(u64& d, u64 a, u64 b) {
    asm("fma.rn.f32x2 %0, %1, %2, %3;" : "=l"(d) : "l"(a), "l"(b), "l"(d));
}
__device__ __forceinline__ float2 unpack2(u64 v) {
    float2 f; asm("mov.b64 {%0, %1}, %2;" : "=f"(f.x), "=f"(f.y) : "l"(v)); return f;
}
__device__ __forceinline__ float fcomp(float4 v, int kk) {
    return (kk==0) ? v.x : (kk==1) ? v.y : (kk==2) ? v.z : v.w;
}

// MUFU sigmoid: ex2.approx + rcp.approx (2 MUFU + ~2 FMA). Saturation-safe.
__device__ __forceinline__ float mufu_sigmoid(float z) {
    float e = __expf(-z);                 // exp via MUFU ex2
    return __fdividef(1.0f, 1.0f + e);    // MUFU rcp
}

// ---------------- CSR build ----------------
__global__ void zero_kernel(int* __restrict__ deg, int* __restrict__ fill) {
    int i = blockIdx.x*blockDim.x + threadIdx.x;
    int4 z = {0,0,0,0};
    ((int4*)deg)[i] = z;
    ((int4*)fill)[i] = z;
}
__global__ void count_kernel(const int* __restrict__ dst1, const int* __restrict__ dst2,
                             int* __restrict__ deg) {
    int e = blockIdx.x*blockDim.x + threadIdx.x;
    if (e < NEDGE) atomicAdd(&deg[dst1[e]], 1);
    else if (e < NEDGE2) atomicAdd(&deg[dst2[e - NEDGE] + NTOT], 1);
}
__global__ void scan_block_kernel(const int* __restrict__ deg, int* __restrict__ rp,
                                  float* __restrict__ dinv, int* __restrict__ bsum) {
    __shared__ int ws[32];
    int tid = threadIdx.x, lane = tid & 31, wid = tid >> 5;
    int gi = blockIdx.x*1024 + tid;
    int v = deg[gi];
    dinv[gi] = rsqrtf((float)(v + 1));
    int x = v;
    #pragma unroll
    for (int off = 1; off < 32; off <<= 1) {
        int t = __shfl_up_sync(0xffffffffu, x, off);
        if (lane >= off) x += t;
    }
    if (lane == 31) ws[wid] = x;
    __syncthreads();
    if (wid == 0) {
        int y = ws[lane];
        #pragma unroll
        for (int off = 1; off < 32; off <<= 1) {
            int t = __shfl_up_sync(0xffffffffu, y, off);
            if (lane >= off) y += t;
        }
        ws[lane] = y;
    }
    __syncthreads();
    int woff = (wid > 0) ? ws[wid-1] : 0;
    rp[gi] = woff + x - v;
    if (tid == 1023) bsum[blockIdx.x] = woff + x;
}
__global__ void scan_add_kernel(int* __restrict__ rp, const int* __restrict__ bsum) {
    __shared__ int off_s;
    if (threadIdx.x == 0) {
        int acc = 0;
        for (int i = 0; i < blockIdx.x; ++i) acc += bsum[i];
        off_s = acc;
    }
    __syncthreads();
    int gi = blockIdx.x*1024 + threadIdx.x;
    rp[gi] += off_s;
    if (gi == 0) rp[NTOT2] = NEDGE2;
}
__global__ void scatter_kernel(const int* __restrict__ src1, const int* __restrict__ dst1,
                               const int* __restrict__ src2, const int* __restrict__ dst2,
                               const int* __restrict__ rp, int* __restrict__ fill,
                               const float* __restrict__ dinv,
                               int* __restrict__ csrc, float* __restrict__ cw) {
    int e = blockIdx.x*blockDim.x + threadIdx.x;
    if (e >= NEDGE2) return;
    int s, d;
    if (e < NEDGE) { s = src1[e]; d = dst1[e]; }
    else { s = src2[e - NEDGE] + NTOT; d = dst2[e - NEDGE] + NTOT; }
    int pos = rp[d] + atomicAdd(&fill[d], 1);
    csrc[pos] = s;
    cw[pos] = dinv[s] * dinv[d];
}

// ---------------- initial features ----------------
__global__ void init_feat_kernel(const float* __restrict__ x1, const int* __restrict__ c1,
                                 const float* __restrict__ rw1,
                                 const float* __restrict__ x2, const int* __restrict__ c2,
                                 const float* __restrict__ rw2,
                                 const float* __restrict__ emb,
                                 const float* __restrict__ W, const float* __restrict__ bias,
                                 float* __restrict__ out) {
    int which = blockIdx.x >> 14;
    int bi = blockIdx.x & 16383;
    const float* x  = which ? x2 : x1;
    const int*   ce = which ? c2 : c1;
    const float* rw = which ? rw2 : rw1;
    int half = threadIdx.x >> 7;
    int f = threadIdx.x & 127;
    int node = bi*2 + half;
    __shared__ float a[2][LDIMS];
    if (f < 29)      a[half][f] = x[node*29 + f];
    else if (f < 45) a[half][f] = emb[ce[node]*16 + (f-29)];
    else if (f < 61) a[half][f] = rw[node*16 + (f-45)];
    __syncthreads();
    float acc = bias[f];
    #pragma unroll
    for (int c = 0; c < LDIMS; ++c)
        acc = fmaf(a[half][c], W[c*FDIM + f], acc);
    out[((size_t)(which*NTOT + node) << 7) + f] = fmaxf(acc, 0.0f);
}

// ---------------- GEMM C[64-tile,128] = op(A) @ W, 128 thr, 8x8 microtile ----------------
__global__ void __launch_bounds__(128, 2)
gemm_aw_kernel(const float* __restrict__ A, const float* __restrict__ W,
               float* __restrict__ C, int relu_a) {
    extern __shared__ float sm[];
    float* As = sm;
    float* Bs = sm + 64*128;
    int tid = threadIdx.x;
    size_t m0 = (size_t)blockIdx.x * 64;

    {
        int r = tid >> 5, c4 = (tid & 31) << 2;
        #pragma unroll
        for (int it = 0; it < 16; ++it) {
            int m = (it << 2) + r;
            float4 v = *(const float4*)(A + (m0 + m)*FDIM + c4);
            if (relu_a) { v.x=fmaxf(v.x,0.f); v.y=fmaxf(v.y,0.f); v.z=fmaxf(v.z,0.f); v.w=fmaxf(v.w,0.f); }
            *(float4*)(As + (m << 7) + c4) = v;
        }
        #pragma unroll
        for (int it = 0; it < 32; ++it) {
            int m = (it << 2) + r;
            *(float4*)(Bs + (m << 7) + c4) = *(const float4*)(W + m*FDIM + c4);
        }
    }
    __syncthreads();

    int tx = tid & 15, ty = tid >> 4;
    u64 acc[8][4] = {};
    #pragma unroll 2
    for (int k0 = 0; k0 < 128; k0 += 4) {
        float4 a4[8];
        #pragma unroll
        for (int i = 0; i < 8; ++i)
            a4[i] = *(float4*)(As + ((ty<<3) + i)*128 + k0);
        #pragma unroll
        for (int kk = 0; kk < 4; ++kk) {
            ulonglong2 q0 = *(ulonglong2*)(Bs + ((k0+kk) << 7) + (tx<<2));
            ulonglong2 q1 = *(ulonglong2*)(Bs + ((k0+kk) << 7) + 64 + (tx<<2));
            u64 bu[4] = {q0.x, q0.y, q1.x, q1.y};
            #pragma unroll
            for (int i = 0; i < 8; ++i) {
                u64 au = pack2(fcomp(a4[i], kk));
                #pragma unroll
                for (int j = 0; j < 4; ++j) ffma2(acc[i][j], au, bu[j]);
            }
        }
    }
    #pragma unroll
    for (int i = 0; i < 8; ++i) {
        int row = (ty<<3) + i;
        float* cp = C + (m0 + row)*FDIM;
        float2 p0 = unpack2(acc[i][0]), p1 = unpack2(acc[i][1]);
        float2 p2 = unpack2(acc[i][2]), p3 = unpack2(acc[i][3]);
        float4 o0 = {p0.x,p0.y,p1.x,p1.y};
        float4 o1 = {p2.x,p2.y,p3.x,p3.y};
        *(float4*)(cp + (tx<<2)) = o0;
        *(float4*)(cp + 64 + (tx<<2)) = o1;
    }
}

// ---------------- GCN aggregation: warp per node, float4 per lane ----------------
__global__ void agg_kernel(const float* __restrict__ h, const float* __restrict__ bias,
                           const int* __restrict__ rp, const int* __restrict__ csrc,
                           const float* __restrict__ cw, const float* __restrict__ dinv,
                           float* __restrict__ out) {
    int n = (blockIdx.x << 3) + (threadIdx.x >> 5);
    int lane = threadIdx.x & 31;
    const float4* h4 = (const float4*)h;
    float di = dinv[n];
    float4 bv = ((const float4*)bias)[lane];
    float4 hv = h4[((size_t)n << 5) + lane];
    float w2 = di*di;
    float4 acc;
    acc.x = fmaf(hv.x, w2, bv.x); acc.y = fmaf(hv.y, w2, bv.y);
    acc.z = fmaf(hv.z, w2, bv.z); acc.w = fmaf(hv.w, w2, bv.w);
    int e = rp[n], e1 = rp[n+1];
    for (; e + 4 <= e1; e += 4) {
        int s0 = csrc[e], s1 = csrc[e+1], s2 = csrc[e+2], s3 = csrc[e+3];
        float w0 = cw[e], w1 = cw[e+1], wv2 = cw[e+2], w3 = cw[e+3];
        float4 v0 = h4[((size_t)s0 << 5) + lane];
        float4 v1 = h4[((size_t)s1 << 5) + lane];
        float4 v2 = h4[((size_t)s2 << 5) + lane];
        float4 v3 = h4[((size_t)s3 << 5) + lane];
        acc.x = fmaf(v0.x, w0, acc.x); acc.y = fmaf(v0.y, w0, acc.y);
        acc.z = fmaf(v0.z, w0, acc.z); acc.w = fmaf(v0.w, w0, acc.w);
        acc.x = fmaf(v1.x, w1, acc.x); acc.y = fmaf(v1.y, w1, acc.y);
        acc.z = fmaf(v1.z, w1, acc.z); acc.w = fmaf(v1.w, w1, acc.w);
        acc.x = fmaf(v2.x, wv2, acc.x); acc.y = fmaf(v2.y, wv2, acc.y);
        acc.z = fmaf(v2.z, wv2, acc.z); acc.w = fmaf(v2.w, wv2, acc.w);
        acc.x = fmaf(v3.x, w3, acc.x); acc.y = fmaf(v3.y, w3, acc.y);
        acc.z = fmaf(v3.z, w3, acc.z); acc.w = fmaf(v3.w, w3, acc.w);
    }
    for (; e < e1; ++e) {
        float w = cw[e];
        float4 v = h4[((size_t)csrc[e] << 5) + lane];
        acc.x = fmaf(v.x, w, acc.x); acc.y = fmaf(v.y, w, acc.y);
        acc.z = fmaf(v.z, w, acc.z); acc.w = fmaf(v.w, w, acc.w);
    }
    ((float4*)out)[((size_t)n << 5) + lane] = acc;
}

// ---------------- fused affinity + 2-anchor Sinkhorn (512 thr, MUFU sigmoid) ----------------
__global__ void __launch_bounds__(512, 1)
aff_sink_kernel(const float* __restrict__ feat, const float* __restrict__ fc,
                const float* __restrict__ Aaff, const int* __restrict__ topk,
                float* __restrict__ sim1, float* __restrict__ sim2) {
    extern __shared__ float smf[];
    float* As = smf;                    // [128][128] Xa then T
    float* Ws = smf + 128*128;          // [128][128] Aaff
    float* Bs = Ws + 128*128;           // [128][APAD] Xb^T
    __shared__ float rmn[16], rmx[16], rbuf[16], bc[2];

    int tid = threadIdx.x;
    int lane = tid & 31, wid = tid >> 5;
    int which = blockIdx.x >> 8;
    int b = blockIdx.x & 255;
    const float* base = which ? fc : feat;
    const float* Xa = base + (size_t)b * LMAT;
    const float* Xb = base + HALF + (size_t)b * LMAT;
    float* P = (which ? sim2 : sim1) + (size_t)b * LMAT;

    {
        int lr = tid >> 5, lc = (tid & 31) << 2;
        #pragma unroll
        for (int it = 0; it < 8; ++it) {
            int m = (it << 4) + lr;
            *(float4*)(As + (m << 7) + lc) = *(const float4*)(Xa + (m << 7) + lc);
            *(float4*)(Ws + (m << 7) + lc) = *(const float4*)(Aaff + (m << 7) + lc);
            float4 vb = *(const float4*)(Xb + (m << 7) + lc);
            Bs[(lc+0)*APAD + m] = vb.x; Bs[(lc+1)*APAD + m] = vb.y;
            Bs[(lc+2)*APAD + m] = vb.z; Bs[(lc+3)*APAD + m] = vb.w;
        }
    }
    __syncthreads();
    int c4 = lane << 2;

    // loop1: T = Xa @ Aaff
    u64 acc[8][2] = {};
    #pragma unroll 2
    for (int k0 = 0; k0 < 128; k0 += 4) {
        float4 a4[8];
        #pragma unroll
        for (int i = 0; i < 8; ++i)
            a4[i] = *(float4*)(As + ((wid<<3) + i)*128 + k0);
        #pragma unroll
        for (int kk = 0; kk < 4; ++kk) {
            ulonglong2 q = *(ulonglong2*)(Ws + ((k0+kk) << 7) + c4);
            #pragma unroll
            for (int i = 0; i < 8; ++i) {
                u64 au = pack2(fcomp(a4[i], kk));
                ffma2(acc[i][0], au, q.x);
                ffma2(acc[i][1], au, q.y);
            }
        }
    }
    __syncthreads();
    #pragma unroll
    for (int i = 0; i < 8; ++i) {
        int row = (wid<<3) + i;
        float2 p0 = unpack2(acc[i][0]), p1 = unpack2(acc[i][1]);
        float4 o = {p0.x, p0.y, p1.x, p1.y};
        *(float4*)(As + (row << 7) + c4) = o;
    }
    __syncthreads();

    // loop2: C = T @ Xb^T
    #pragma unroll
    for (int i = 0; i < 8; ++i) { acc[i][0] = 0ull; acc[i][1] = 0ull; }
    #pragma unroll 2
    for (int k0 = 0; k0 < 128; k0 += 4) {
        float4 a4[8];
        #pragma unroll
        for (int i = 0; i < 8; ++i)
            a4[i] = *(float4*)(As + ((wid<<3) + i)*128 + k0);
        #pragma unroll
        for (int kk = 0; kk < 4; ++kk) {
            ulonglong2 q = *(ulonglong2*)(Bs + (k0+kk)*APAD + c4);
            #pragma unroll
            for (int i = 0; i < 8; ++i) {
                u64 au = pack2(fcomp(a4[i], kk));
                ffma2(acc[i][0], au, q.x);
                ffma2(acc[i][1], au, q.y);
            }
        }
    }

    float za[32];
    float mn = 3.4e38f, mx = -3.4e38f;
    #pragma unroll
    for (int i = 0; i < 8; ++i) {
        float2 p0 = unpack2(acc[i][0]), p1 = unpack2(acc[i][1]);
        za[i*4 + 0] = p0.x; za[i*4 + 1] = p0.y;
        za[i*4 + 2] = p1.x; za[i*4 + 3] = p1.y;
        mn = fminf(mn, fminf(fminf(p0.x, p0.y), fminf(p1.x, p1.y)));
        mx = fmaxf(mx, fmaxf(fmaxf(p0.x, p0.y), fmaxf(p1.x, p1.y)));
    }
    #pragma unroll
    for (int off = 16; off; off >>= 1) {
        mn = fminf(mn, __shfl_xor_sync(0xffffffffu, mn, off));
        mx = fmaxf(mx, __shfl_xor_sync(0xffffffffu, mx, off));
    }
    if (lane == 0) { rmn[wid] = mn; rmx[wid] = mx; }
    __syncthreads();
    if (tid == 0) {
        float m1 = rmn[0], m2 = rmx[0];
        for (int q = 1; q < 16; ++q) { m1 = fminf(m1, rmn[q]); m2 = fmaxf(m2, rmx[q]); }
        bc[0] = m1 + m2;
    }
    __syncthreads();
    float Cc = bc[0];
    #pragma unroll
    for (int l = 0; l < 32; ++l) za[l] = fmaf(2.0f, za[l], -Cc);

    float kf = 0.5f * (float)(*topk);
    const float Lf = (float)LMAT;
    float lk = logf(kf / (Lf - kf));
    float delta = 0.0f, scale = 0.0f;
    for (int it = 0; it < SK_ITERS; ++it) {
        float T = 0.0f;
        if (it < SK_ITERS - 1) {
            #pragma unroll
            for (int l = 0; l < 32; ++l) T += mufu_sigmoid(za[l] + delta);
        } else {
            #pragma unroll
            for (int l = 0; l < 32; ++l) { za[l] = mufu_sigmoid(za[l] + delta); T += za[l]; }
        }
        #pragma unroll
        for (int off = 16; off; off >>= 1)
            T += __shfl_xor_sync(0xffffffffu, T, off);
        if (lane == 0) rbuf[wid] = T;
        __syncthreads();
        if (tid == 0) {
            float s = 0.0f;
            for (int q = 0; q < 16; ++q) s += rbuf[q];
            bc[1] = s;
        }
        __syncthreads();
        float Tall = bc[1];
        if (it < SK_ITERS - 1) delta += lk + logf((Lf - Tall) / Tall);
        else scale = kf / Tall;
        __syncthreads();
    }

    #pragma unroll
    for (int i = 0; i < 8; ++i) {
        int row = (wid<<3) + i;
        float4 o = {scale * za[i*4 + 0], scale * za[i*4 + 1],
                    scale * za[i*4 + 2], scale * za[i*4 + 3]};
        *(float4*)(P + (row << 7) + c4) = o;
    }
}

// ---------------- graph features + scorer ----------------
__global__ void gf_kernel(const float* __restrict__ feat, const float* __restrict__ fa,
                          const float* __restrict__ fb, const float* __restrict__ fcv,
                          float* __restrict__ scores) {
    int b = blockIdx.x;
    int tid = threadIdx.x;
    int job = tid >> 5, lane = tid & 31;
    int buf = job & 3;
    const float* p = (buf==0?feat:buf==1?fa:buf==2?fb:fcv);
    if (job < 4) {
        const float4* p4 = (const float4*)(p + (((size_t)b*NNODE) << 7)) + lane;
        float4 s = {0,0,0,0};
        #pragma unroll 4
        for (int n = 0; n < NNODE; ++n) {
            float4 v = p4[n << 5];
            s.x += v.x; s.y += v.y; s.z += v.z; s.w += v.w;
        }
        ((float4*)(scores + b*1024 + buf*128))[lane] = s;
    } else {
        const float4* p4 = (const float4*)(p + HALF + (((size_t)b*NNODE) << 7)) + lane;
        float4 m = {-3.4e38f,-3.4e38f,-3.4e38f,-3.4e38f};
        #pragma unroll 4
        for (int n = 0; n < NNODE; ++n) {
            float4 v = p4[n << 5];
            m.x = fmaxf(m.x, v.x); m.y = fmaxf(m.y, v.y);
            m.z = fmaxf(m.z, v.z); m.w = fmaxf(m.w, v.w);
        }
        ((float4*)(scores + b*1024 + 512 + buf*128))[lane] = m;
    }
}

__global__ void score_kernel(const float* __restrict__ scores,
                             const float* __restrict__ W1, const float* __restrict__ b1,
                             const float* __restrict__ W2, const float* __restrict__ b2,
                             float* __restrict__ ged) {
    int b = blockIdx.x;
    int j = threadIdx.x;
    __shared__ float sv[1024];
    __shared__ float rr[2];
    for (int i = j; i < 1024; i += 64) sv[i] = scores[b*1024 + i];
    __syncthreads();
    float acc = b1[j];
    #pragma unroll 8
    for (int i = 0; i < 1024; ++i)
        acc = fmaf(sv[i], W1[i*64 + j], acc);
    float pv = fmaxf(acc, 0.0f) * W2[j];
    #pragma unroll
    for (int off = 16; off; off >>= 1)
        pv += __shfl_xor_sync(0xffffffffu, pv, off);
    if ((j & 31) == 0) rr[j >> 5] = pv;
    __syncthreads();
    if (j == 0) {
        float v = rr[0] + rr[1] + b2[0];
        ged[b] = 1.0f / (1.0f + expf(-v));
    }
}

// ---------------- streams/events ----------------
static cudaStream_t g_s1 = nullptr;
static cudaEvent_t g_evFork = nullptr, g_evCsr = nullptr, g_evFc = nullptr, g_evTail = nullptr;

extern "C" void kernel_launch(void* const* d_in, const int* in_sizes, int n_in,
                              void* d_out, int out_size) {
    const float* x1    = (const float*)d_in[0];
    const int*   cent1 = (const int*)d_in[1];
    const float* rw1   = (const float*)d_in[2];
    const int*   src1  = (const int*)d_in[3];
    const int*   dst1  = (const int*)d_in[4];
    const float* x2    = (const float*)d_in[5];
    const int*   cent2 = (const int*)d_in[6];
    const float* rw2   = (const float*)d_in[7];
    const int*   src2  = (const int*)d_in[8];
    const int*   dst2  = (const int*)d_in[9];
    const float* emb   = (const float*)d_in[10];
    const float* initW = (const float*)d_in[11];
    const float* initb = (const float*)d_in[12];
    const float* W1    = (const float*)d_in[13];
    const float* b1    = (const float*)d_in[14];
    const float* W2    = (const float*)d_in[15];
    const float* b2    = (const float*)d_in[16];
    const float* W3    = (const float*)d_in[17];
    const float* b3    = (const float*)d_in[18];
    const float* Aaff  = (const float*)d_in[19];
    const float* scW1  = (const float*)d_in[20];
    const float* scb1  = (const float*)d_in[21];
    const float* scW2  = (const float*)d_in[22];
    const float* scb2  = (const float*)d_in[23];
    const int*   topk  = (const int*)d_in[24];

    Scratch* S = nullptr;
    cudaGetSymbolAddress((void**)&S, g_scratch);

    float* out  = (float*)d_out;
    float* ged  = out;
    float* sim1 = out + BATCH;
    float* sim2 = out + BATCH + (size_t)BATCH * LMAT;

    if (g_s1 == nullptr) {
        cudaStreamCreateWithFlags(&g_s1, cudaStreamNonBlocking);
        cudaEventCreateWithFlags(&g_evFork, cudaEventDisableTiming);
        cudaEventCreateWithFlags(&g_evCsr,  cudaEventDisableTiming);
        cudaEventCreateWithFlags(&g_evFc,   cudaEventDisableTiming);
        cudaEventCreateWithFlags(&g_evTail, cudaEventDisableTiming);
    }
    cudaStream_t s0 = 0, s1 = g_s1;

    cudaFuncSetAttribute(gemm_aw_kernel,  cudaFuncAttributeMaxDynamicSharedMemorySize, SMEM_G);
    cudaFuncSetAttribute(aff_sink_kernel, cudaFuncAttributeMaxDynamicSharedMemorySize, SMEM_FUSE);

    cudaEventRecord(g_evFork, s0);
    cudaStreamWaitEvent(s1, g_evFork, 0);

    init_feat_kernel<<<NTOT, 256, 0, s0>>>(x1, cent1, rw1, x2, cent2, rw2,
                                           emb, initW, initb, S->feat);            // 1 (s0)
    zero_kernel<<<64, 256, 0, s1>>>(S->deg, S->fill);                              // 2 (s1)
    count_kernel<<<NEDGE2/256, 256, 0, s1>>>(dst1, dst2, S->deg);                  // 3 (s1)
    gemm_aw_kernel<<<NTOT2/64, 128, SMEM_G, s0>>>(S->feat, W1, S->htmp, 0);        // 4 (s0) <- profiled
    scan_block_kernel<<<64, 1024, 0, s1>>>(S->deg, S->rp, S->dinv, S->bsum);       // 5 (s1)
    scan_add_kernel<<<64, 1024, 0, s1>>>(S->rp, S->bsum);                          // 6 (s1)
    scatter_kernel<<<NEDGE2/256, 256, 0, s1>>>(src1, dst1, src2, dst2, S->rp,
                                               S->fill, S->dinv, S->csrc, S->cw);  // 7 (s1)
    cudaEventRecord(g_evCsr, s1);
    cudaStreamWaitEvent(s0, g_evCsr, 0);

    agg_kernel<<<NTOT2/8, 256, 0, s0>>>(S->htmp, b1, S->rp, S->csrc, S->cw, S->dinv, S->fa);
    gemm_aw_kernel<<<NTOT2/64, 128, SMEM_G, s0>>>(S->fa, W2, S->htmp, 1);
    agg_kernel<<<NTOT2/8, 256, 0, s0>>>(S->htmp, b2, S->rp, S->csrc, S->cw, S->dinv, S->fb);
    gemm_aw_kernel<<<NTOT2/64, 128, SMEM_G, s0>>>(S->fb, W3, S->htmp, 1);
    agg_kernel<<<NTOT2/8, 256, 0, s0>>>(S->htmp, b3, S->rp, S->csrc, S->cw, S->dinv, S->fc);

    cudaEventRecord(g_evFc, s0);
    cudaStreamWaitEvent(s1, g_evFc, 0);
    aff_sink_kernel<<<2*BATCH, 512, SMEM_FUSE, s0>>>(S->feat, S->fc, Aaff, topk, sim1, sim2);
    gf_kernel<<<BATCH, 256, 0, s1>>>(S->feat, S->fa, S->fb, S->fc, S->scores);
    score_kernel<<<BATCH, 64, 0, s1>>>(S->scores, scW1, scb1, scW2, scb2, ged);
    cudaEventRecord(g_evTail, s1);
    cudaStreamWaitEvent(s0, g_evTail, 0);
}